// round 2
// baseline (speedup 1.0000x reference)
#include <cuda_runtime.h>
#include <cuda_bf16.h>
#include <math.h>

#define Bc 8
#define N1c 4096
#define N2c 2048
#define Hc 64
#define Kc 8

// ---------------- device scratch (no cudaMalloc allowed) ----------------
__device__ float    g_h1 [Bc*N1c*Hc];
__device__ float    g_x2a[Bc*N1c];
__device__ int      g_nbr1[Bc*N1c*Kc];
__device__ float    g_Pd1[Bc*N1c*96];
__device__ float    g_Ps1[Bc*N1c*96];
__device__ unsigned g_agg1[Bc*N1c*Hc];
__device__ float    g_h3 [Bc*N2c*Hc];
__device__ float    g_x2b[Bc*N2c];
__device__ int      g_nbr2[Bc*N2c*Kc];
__device__ float    g_Pd2[Bc*N2c*96];
__device__ float    g_Ps2[Bc*N2c*96];
__device__ unsigned g_agg2[Bc*N2c*Hc];

// ---------------- helpers ----------------
__device__ __forceinline__ float eluf(float x) { return x > 0.f ? x : expm1f(x); }

__device__ __forceinline__ unsigned encf(float f) {
    unsigned u = __float_as_uint(f);
    return (u & 0x80000000u) ? ~u : (u | 0x80000000u);
}
__device__ __forceinline__ float decf(unsigned u) {
    return __uint_as_float((u & 0x80000000u) ? (u ^ 0x80000000u) : ~u);
}

// packed dual fp32 FMA: c += a*b elementwise on f32x2 (sm_103a)
__device__ __forceinline__ void ffma2(float2& c, const float2 a, const float2 b) {
    unsigned long long* cp = reinterpret_cast<unsigned long long*>(&c);
    asm("fma.rn.f32x2 %0, %1, %2, %0;"
        : "+l"(*cp)
        : "l"(*reinterpret_cast<const unsigned long long*>(&a)),
          "l"(*reinterpret_cast<const unsigned long long*>(&b)));
}

// ---------------- zero init ----------------
__global__ void zero_kernel(unsigned* p, int n) {
    for (int i = blockIdx.x * blockDim.x + threadIdx.x; i < n; i += gridDim.x * blockDim.x)
        p[i] = 0u;
}

// ---------------- input MLP ----------------
__global__ void input_mlp_kernel(const float* __restrict__ x, const float* __restrict__ nrm,
                                 const float* __restrict__ w1, const float* __restrict__ b1,
                                 const float* __restrict__ w2, const float* __restrict__ b2,
                                 float* __restrict__ h, float* __restrict__ x2) {
    __shared__ float sw1[10 * 32], sb1[32], sw2[32 * 64], sb2[64], snrm[10];
    for (int idx = threadIdx.x; idx < 320; idx += blockDim.x) sw1[idx] = w1[idx];
    for (int idx = threadIdx.x; idx < 2048; idx += blockDim.x) sw2[idx] = w2[idx];
    if (threadIdx.x < 32) sb1[threadIdx.x] = b1[threadIdx.x];
    if (threadIdx.x < 64) sb2[threadIdx.x] = b2[threadIdx.x];
    if (threadIdx.x < 10) snrm[threadIdx.x] = nrm[threadIdx.x];
    __syncthreads();
    int n = blockIdx.x * blockDim.x + threadIdx.x;
    float xv[10];
#pragma unroll
    for (int c = 0; c < 10; c++) xv[c] = x[n * 10 + c] * snrm[c];
    float a[32];
#pragma unroll
    for (int o = 0; o < 32; o++) {
        float acc = sb1[o];
#pragma unroll
        for (int c = 0; c < 10; c++) acc = fmaf(xv[c], sw1[c * 32 + o], acc);
        a[o] = eluf(acc);
    }
    float ss = 0.f;
#pragma unroll 4
    for (int o = 0; o < 64; o++) {
        float acc = sb2[o];
#pragma unroll
        for (int c = 0; c < 32; c++) acc = fmaf(a[c], sw2[c * 64 + o], acc);
        acc = eluf(acc);
        h[(size_t)n * 64 + o] = acc;
        ss = fmaf(acc, acc, ss);
    }
    x2[n] = ss;
}

// ---------------- register-tiled brute-force kNN ----------------
// Block: 64 queries x full scan of N candidates in 128-wide tiles.
// 128 threads (16 tx x 8 ty), micro-tile 8 rows x 8 cols, f32x2 packed over k.
#define QS_STRIDE 66
#define CS_STRIDE 66
#define DS_STRIDE 130
#define KNN_SMEM_FLOATS (64*QS_STRIDE + 128*CS_STRIDE + 64*DS_STRIDE + 128)

template <int N>
__global__ void __launch_bounds__(128) knn_kernel(const float* __restrict__ h,
                                                  const float* __restrict__ x2,
                                                  int* __restrict__ nbr) {
    extern __shared__ float sm[];
    float* Qs   = sm;                       // [64][66]
    float* Cs   = Qs + 64 * QS_STRIDE;      // [128][66]
    float* Ds   = Cs + 128 * CS_STRIDE;     // [64][130]
    float* sx2c = Ds + 64 * DS_STRIDE;      // [128]

    const int b  = blockIdx.y;
    const int i0 = blockIdx.x * 64;
    const float* hb = h + (size_t)b * N * 64;
    const int tid = threadIdx.x;
    const int tx = tid & 15;      // 0..15 -> candidate cols tx+16v
    const int ty = tid >> 4;      // 0..7  -> query rows ty+8u

    // load Q tile
    for (int idx = tid; idx < 64 * 64; idx += 128) {
        int r = idx >> 6, c = idx & 63;
        Qs[r * QS_STRIDE + c] = hb[(size_t)(i0 + r) * 64 + c];
    }

    const int qrow  = tid & 63;   // query this thread tracks in phase B
    const int chalf = tid >> 6;   // 0: cols 0..63, 1: cols 64..127
    const float x2i = x2[b * N + i0 + qrow];
    const int self  = i0 + qrow;

    float bd[8]; int bi[8];
#pragma unroll
    for (int r = 0; r < 8; r++) { bd[r] = 3e38f; bi[r] = 0; }
    __syncthreads();

    for (int jt = 0; jt < N; jt += 128) {
        // load C tile (coalesced row copies)
        for (int idx = tid; idx < 128 * 64; idx += 128) {
            int r = idx >> 6, c = idx & 63;
            Cs[r * CS_STRIDE + c] = hb[(size_t)(jt + r) * 64 + c];
        }
        sx2c[tid] = x2[b * N + jt + tid];
        __syncthreads();

        // phase A: 64x128 dot tile, f32x2 packed over k
        float2 acc[8][8];
#pragma unroll
        for (int u = 0; u < 8; u++)
#pragma unroll
            for (int v = 0; v < 8; v++) acc[u][v] = make_float2(0.f, 0.f);

#pragma unroll 1
        for (int k = 0; k < 64; k += 2) {
            float2 a[8], bb[8];
#pragma unroll
            for (int u = 0; u < 8; u++)
                a[u] = *(const float2*)&Qs[(ty + 8 * u) * QS_STRIDE + k];
#pragma unroll
            for (int v = 0; v < 8; v++)
                bb[v] = *(const float2*)&Cs[(tx + 16 * v) * CS_STRIDE + k];
#pragma unroll
            for (int u = 0; u < 8; u++)
#pragma unroll
                for (int v = 0; v < 8; v++) ffma2(acc[u][v], a[u], bb[v]);
        }
#pragma unroll
        for (int u = 0; u < 8; u++)
#pragma unroll
            for (int v = 0; v < 8; v++)
                Ds[(ty + 8 * u) * DS_STRIDE + tx + 16 * v] = acc[u][v].x + acc[u][v].y;
        __syncthreads();

        // phase B: each thread scans 64 candidates of its query
        const float* dr = Ds + qrow * DS_STRIDE + chalf * 64;
        const float* sx = sx2c + chalf * 64;
        const int jb = jt + chalf * 64;
#pragma unroll 1
        for (int jj = 0; jj < 64; jj++) {
            float d = x2i + sx[jj] - 2.f * dr[jj];
            int j = jb + jj;
            if (d < bd[7] && j != self) {
                bd[7] = d; bi[7] = j;
#pragma unroll
                for (int r = 7; r > 0; --r) {
                    if (bd[r] < bd[r - 1]) {
                        float tb = bd[r]; bd[r] = bd[r - 1]; bd[r - 1] = tb;
                        int ti = bi[r]; bi[r] = bi[r - 1]; bi[r - 1] = ti;
                    }
                }
            }
        }
        __syncthreads();
    }

    // merge the two half-scans per query: lexicographic (d, idx)
    float* stg = Cs;  // reuse
    if (chalf == 1) {
#pragma unroll
        for (int r = 0; r < 8; r++) {
            stg[qrow * 16 + r] = bd[r];
            ((int*)stg)[qrow * 16 + 8 + r] = bi[r];
        }
    }
    __syncthreads();
    if (chalf == 0) {
        int oi[8];
        int pa = 0, pb = 0;
#pragma unroll
        for (int r = 0; r < 8; r++) {
            float da = bd[pa];
            int ia = bi[pa];
            float db = stg[qrow * 16 + pb];
            int ib = ((int*)stg)[qrow * 16 + 8 + pb];
            bool ta = (da < db) || (da == db && ia < ib);
            oi[r] = ta ? ia : ib;
            if (ta) pa++; else pb++;
        }
#pragma unroll
        for (int r = 0; r < 8; r++)
            nbr[(size_t)(b * N + i0 + qrow) * 8 + r] = oi[r];
    }
}

// ---------------- per-node projections for EdgeConv decomposition ----------------
__global__ void proj_kernel(const float* __restrict__ h, const float* __restrict__ wa,
                            float* __restrict__ Pd, float* __restrict__ Ps, int NB) {
    __shared__ float Wd[64 * 96];
    __shared__ float Ws[64 * 96];
    for (int idx = threadIdx.x; idx < 64 * 96; idx += blockDim.x) {
        float top = wa[idx];
        float bot = wa[64 * 96 + idx];
        Wd[idx] = top - bot;
        Ws[idx] = bot;
    }
    __syncthreads();
    int warp = (blockIdx.x * blockDim.x + threadIdx.x) >> 5;
    int lane = threadIdx.x & 31;
    int nwarps = (gridDim.x * blockDim.x) >> 5;
    for (int n = warp; n < NB; n += nwarps) {
        float h0 = h[(size_t)n * 64 + lane];
        float h1 = h[(size_t)n * 64 + 32 + lane];
        float d0 = 0, d1 = 0, d2 = 0, s0 = 0, s1 = 0, s2 = 0;
#pragma unroll
        for (int c = 0; c < 64; c++) {
            float hc = __shfl_sync(0xffffffffu, (c < 32) ? h0 : h1, c & 31);
            const float* wd = &Wd[c * 96 + lane];
            const float* ws = &Ws[c * 96 + lane];
            d0 = fmaf(hc, wd[0], d0);  d1 = fmaf(hc, wd[32], d1);  d2 = fmaf(hc, wd[64], d2);
            s0 = fmaf(hc, ws[0], s0);  s1 = fmaf(hc, ws[32], s1);  s2 = fmaf(hc, ws[64], s2);
        }
        Pd[(size_t)n * 96 + lane] = d0; Pd[(size_t)n * 96 + lane + 32] = d1; Pd[(size_t)n * 96 + lane + 64] = d2;
        Ps[(size_t)n * 96 + lane] = s0; Ps[(size_t)n * 96 + lane + 32] = s1; Ps[(size_t)n * 96 + lane + 64] = s2;
    }
}

// ---------------- EdgeConv ----------------
__global__ void __launch_bounds__(256) edgeconv_kernel(
    const float* __restrict__ Pd, const float* __restrict__ Ps,
    const float* __restrict__ b1, const float* __restrict__ w2,
    const float* __restrict__ b2, const int* __restrict__ nbr,
    unsigned* __restrict__ agg, int Nn) {
    __shared__ float W2s[96 * 64];
    __shared__ float b2s[64];
    __shared__ float hidF[8][96];
    __shared__ float hidR[8][96];
    for (int idx = threadIdx.x; idx < 96 * 64; idx += blockDim.x) W2s[idx] = w2[idx];
    if (threadIdx.x < 64) b2s[threadIdx.x] = b2[threadIdx.x];
    __syncthreads();
    const int w = threadIdx.x >> 5, lane = threadIdx.x & 31;
    const int gn = blockIdx.x * 8 + w;
    const int b = gn / Nn;
    const float* pdi_p = Pd + (size_t)gn * 96;
    const float* psi_p = Ps + (size_t)gn * 96;
    float pdi0 = pdi_p[lane], pdi1 = pdi_p[lane + 32], pdi2 = pdi_p[lane + 64];
    float psi0 = psi_p[lane], psi1 = psi_p[lane + 32], psi2 = psi_p[lane + 64];
    float b10 = b1[lane], b11 = b1[lane + 32], b12 = b1[lane + 64];
    int nk = (lane < 8) ? nbr[(size_t)gn * 8 + lane] : 0;
    unsigned fm0 = 0u, fm1 = 0u;
#pragma unroll 1
    for (int k = 0; k < 8; k++) {
        int j = __shfl_sync(0xffffffffu, nk, k);
        size_t jg = (size_t)b * Nn + j;
        const float* pdj = Pd + jg * 96;
        const float* psj = Ps + jg * 96;
        float pj0 = pdj[lane], pj1 = pdj[lane + 32], pj2 = pdj[lane + 64];
        float sj0 = psj[lane], sj1 = psj[lane + 32], sj2 = psj[lane + 64];
        hidF[w][lane]      = eluf(pdi0 + sj0 + b10);
        hidF[w][lane + 32] = eluf(pdi1 + sj1 + b11);
        hidF[w][lane + 64] = eluf(pdi2 + sj2 + b12);
        hidR[w][lane]      = eluf(pj0 + psi0 + b10);
        hidR[w][lane + 32] = eluf(pj1 + psi1 + b11);
        hidR[w][lane + 64] = eluf(pj2 + psi2 + b12);
        __syncwarp();
        float aF0 = b2s[lane], aF1 = b2s[lane + 32];
        float aR0 = aF0, aR1 = aF1;
#pragma unroll 8
        for (int hh = 0; hh < 96; hh++) {
            float vf = hidF[w][hh], vr = hidR[w][hh];
            float w0 = W2s[hh * 64 + lane], w1 = W2s[hh * 64 + lane + 32];
            aF0 = fmaf(vf, w0, aF0); aF1 = fmaf(vf, w1, aF1);
            aR0 = fmaf(vr, w0, aR0); aR1 = fmaf(vr, w1, aR1);
        }
        __syncwarp();
        unsigned e0 = encf(eluf(aF0)), e1 = encf(eluf(aF1));
        fm0 = max(fm0, e0); fm1 = max(fm1, e1);
        atomicMax(agg + jg * 64 + lane,      encf(eluf(aR0)));
        atomicMax(agg + jg * 64 + lane + 32, encf(eluf(aR1)));
    }
    atomicMax(agg + (size_t)gn * 64 + lane,      fm0);
    atomicMax(agg + (size_t)gn * 64 + lane + 32, fm1);
}

// ---------------- decode + pairwise max pool + sq-norm ----------------
__global__ void pool_kernel(const unsigned* __restrict__ agg, float* __restrict__ h3,
                            float* __restrict__ x2b) {
    int w = (blockIdx.x * blockDim.x + threadIdx.x) >> 5;
    int lane = threadIdx.x & 31;
    int b = w / N2c;
    int i = w - b * N2c;
    size_t s0 = ((size_t)(b * N1c + 2 * i)) * 64;
    float ss = 0.f;
#pragma unroll
    for (int r = 0; r < 2; r++) {
        int c = lane + 32 * r;
        float v = fmaxf(decf(agg[s0 + c]), decf(agg[s0 + 64 + c]));
        h3[(size_t)w * 64 + c] = v;
        ss = fmaf(v, v, ss);
    }
    for (int o = 16; o > 0; o >>= 1) ss += __shfl_down_sync(0xffffffffu, ss, o);
    if (lane == 0) x2b[w] = ss;
}

// ---------------- global max pool + head MLP ----------------
__global__ void final_kernel(const unsigned* __restrict__ agg,
                             const float* __restrict__ w1, const float* __restrict__ bb1,
                             const float* __restrict__ w2, const float* __restrict__ bb2,
                             const float* __restrict__ w3, const float* __restrict__ bb3,
                             float* __restrict__ out) {
    __shared__ float red[256];
    __shared__ float gv[64], t1[64], t2[32];
    int b = blockIdx.x;
    int c = threadIdx.x & 63, grp = threadIdx.x >> 6;
    float m = -3e38f;
    for (int n = grp; n < N2c; n += 4)
        m = fmaxf(m, decf(agg[((size_t)(b * N2c + n)) * 64 + c]));
    red[threadIdx.x] = m;
    __syncthreads();
    if (threadIdx.x < 64) {
        m = fmaxf(fmaxf(red[threadIdx.x], red[threadIdx.x + 64]),
                  fmaxf(red[threadIdx.x + 128], red[threadIdx.x + 192]));
        gv[threadIdx.x] = m;
    }
    __syncthreads();
    if (threadIdx.x < 64) {
        float acc = bb1[threadIdx.x];
#pragma unroll
        for (int cc = 0; cc < 64; cc++) acc = fmaf(gv[cc], w1[cc * 64 + threadIdx.x], acc);
        t1[threadIdx.x] = eluf(acc);
    }
    __syncthreads();
    if (threadIdx.x < 32) {
        float acc = bb2[threadIdx.x];
#pragma unroll
        for (int cc = 0; cc < 64; cc++) acc = fmaf(t1[cc], w2[cc * 32 + threadIdx.x], acc);
        t2[threadIdx.x] = eluf(acc);
    }
    __syncthreads();
    if (threadIdx.x == 0) {
        float o0 = bb3[0], o1 = bb3[1];
#pragma unroll
        for (int cc = 0; cc < 32; cc++) {
            o0 = fmaf(t2[cc], w3[cc * 2 + 0], o0);
            o1 = fmaf(t2[cc], w3[cc * 2 + 1], o1);
        }
        float met = fmaxf(o0, 0.f) + log1pf(expf(-fabsf(o0)));
        float sig = 1.f / (1.f + expf(-o1));
        float phi = 3.14159265358979323846f * (2.f * sig - 1.f);
        out[b * 2 + 0] = met;
        out[b * 2 + 1] = phi;
    }
}

// ---------------- launch ----------------
extern "C" void kernel_launch(void* const* d_in, const int* in_sizes, int n_in,
                              void* d_out, int out_size) {
    const float* x      = (const float*)d_in[0];
    const float* nrm    = (const float*)d_in[1];
    const float* w_in1  = (const float*)d_in[2];
    const float* b_in1  = (const float*)d_in[3];
    const float* w_in2  = (const float*)d_in[4];
    const float* b_in2  = (const float*)d_in[5];
    const float* w_c1a  = (const float*)d_in[6];
    const float* b_c1a  = (const float*)d_in[7];
    const float* w_c1b  = (const float*)d_in[8];
    const float* b_c1b  = (const float*)d_in[9];
    const float* w_c2a  = (const float*)d_in[10];
    const float* b_c2a  = (const float*)d_in[11];
    const float* w_c2b  = (const float*)d_in[12];
    const float* b_c2b  = (const float*)d_in[13];
    const float* w_o1   = (const float*)d_in[14];
    const float* b_o1   = (const float*)d_in[15];
    const float* w_o2   = (const float*)d_in[16];
    const float* b_o2   = (const float*)d_in[17];
    const float* w_o3   = (const float*)d_in[18];
    const float* b_o3   = (const float*)d_in[19];
    float* out = (float*)d_out;

    float *h1, *x2a, *Pd1, *Ps1, *h3, *x2b, *Pd2, *Ps2;
    int *nbr1, *nbr2;
    unsigned *agg1, *agg2;
    cudaGetSymbolAddress((void**)&h1,   g_h1);
    cudaGetSymbolAddress((void**)&x2a,  g_x2a);
    cudaGetSymbolAddress((void**)&nbr1, g_nbr1);
    cudaGetSymbolAddress((void**)&Pd1,  g_Pd1);
    cudaGetSymbolAddress((void**)&Ps1,  g_Ps1);
    cudaGetSymbolAddress((void**)&agg1, g_agg1);
    cudaGetSymbolAddress((void**)&h3,   g_h3);
    cudaGetSymbolAddress((void**)&x2b,  g_x2b);
    cudaGetSymbolAddress((void**)&nbr2, g_nbr2);
    cudaGetSymbolAddress((void**)&Pd2,  g_Pd2);
    cudaGetSymbolAddress((void**)&Ps2,  g_Ps2);
    cudaGetSymbolAddress((void**)&agg2, g_agg2);

    const int knn_smem = KNN_SMEM_FLOATS * sizeof(float);
    cudaFuncSetAttribute(knn_kernel<N1c>, cudaFuncAttributeMaxDynamicSharedMemorySize, knn_smem);
    cudaFuncSetAttribute(knn_kernel<N2c>, cudaFuncAttributeMaxDynamicSharedMemorySize, knn_smem);

    zero_kernel<<<1024, 256>>>(agg1, Bc * N1c * Hc);
    zero_kernel<<<1024, 256>>>(agg2, Bc * N2c * Hc);

    input_mlp_kernel<<<(Bc * N1c) / 128, 128>>>(x, nrm, w_in1, b_in1, w_in2, b_in2, h1, x2a);

    knn_kernel<N1c><<<dim3(N1c / 64, Bc), 128, knn_smem>>>(h1, x2a, nbr1);
    proj_kernel<<<(Bc * N1c) / 8, 256>>>(h1, w_c1a, Pd1, Ps1, Bc * N1c);
    edgeconv_kernel<<<(Bc * N1c) / 8, 256>>>(Pd1, Ps1, b_c1a, w_c1b, b_c1b, nbr1, agg1, N1c);

    pool_kernel<<<(Bc * N2c) / 8, 256>>>(agg1, h3, x2b);

    knn_kernel<N2c><<<dim3(N2c / 64, Bc), 128, knn_smem>>>(h3, x2b, nbr2);
    proj_kernel<<<(Bc * N2c) / 8, 256>>>(h3, w_c2a, Pd2, Ps2, Bc * N2c);
    edgeconv_kernel<<<(Bc * N2c) / 8, 256>>>(Pd2, Ps2, b_c2a, w_c2b, b_c2b, nbr2, agg2, N2c);

    final_kernel<<<Bc, 256>>>(agg2, w_o1, b_o1, w_o2, b_o2, w_o3, b_o3, out);
}

// round 3
// speedup vs baseline: 1.1826x; 1.1826x over previous
#include <cuda_runtime.h>
#include <cuda_bf16.h>
#include <math.h>

#define Bc 8
#define N1c 4096
#define N2c 2048
#define Hc 64
#define Kc 8
#define CH 4   // candidate chunks per kNN pass

// ---------------- device scratch (no cudaMalloc allowed) ----------------
__device__ float    g_h1 [Bc*N1c*Hc];
__device__ float    g_x2a[Bc*N1c];
__device__ int      g_nbr1[Bc*N1c*Kc];
__device__ float    g_Pd1[Bc*N1c*96];
__device__ float    g_Ps1[Bc*N1c*96];
__device__ unsigned g_agg1[Bc*N1c*Hc];
__device__ float    g_h3 [Bc*N2c*Hc];
__device__ float    g_x2b[Bc*N2c];
__device__ int      g_nbr2[Bc*N2c*Kc];
__device__ float    g_Pd2[Bc*N2c*96];
__device__ float    g_Ps2[Bc*N2c*96];
__device__ unsigned g_agg2[Bc*N2c*Hc];
__device__ float    g_pd1[Bc*N1c*CH*Kc];
__device__ int      g_pi1[Bc*N1c*CH*Kc];
__device__ float    g_pd2[Bc*N2c*CH*Kc];
__device__ int      g_pi2[Bc*N2c*CH*Kc];

// ---------------- helpers ----------------
__device__ __forceinline__ float eluf(float x) { return x > 0.f ? x : expm1f(x); }

__device__ __forceinline__ unsigned encf(float f) {
    unsigned u = __float_as_uint(f);
    return (u & 0x80000000u) ? ~u : (u | 0x80000000u);
}
__device__ __forceinline__ float decf(unsigned u) {
    return __uint_as_float((u & 0x80000000u) ? (u ^ 0x80000000u) : ~u);
}

// ---------------- zero init ----------------
__global__ void zero_kernel(unsigned* p, int n) {
    for (int i = blockIdx.x * blockDim.x + threadIdx.x; i < n; i += gridDim.x * blockDim.x)
        p[i] = 0u;
}

// ---------------- input MLP ----------------
__global__ void input_mlp_kernel(const float* __restrict__ x, const float* __restrict__ nrm,
                                 const float* __restrict__ w1, const float* __restrict__ b1,
                                 const float* __restrict__ w2, const float* __restrict__ b2,
                                 float* __restrict__ h, float* __restrict__ x2) {
    __shared__ float sw1[10 * 32], sb1[32], sw2[32 * 64], sb2[64], snrm[10];
    for (int idx = threadIdx.x; idx < 320; idx += blockDim.x) sw1[idx] = w1[idx];
    for (int idx = threadIdx.x; idx < 2048; idx += blockDim.x) sw2[idx] = w2[idx];
    if (threadIdx.x < 32) sb1[threadIdx.x] = b1[threadIdx.x];
    if (threadIdx.x < 64) sb2[threadIdx.x] = b2[threadIdx.x];
    if (threadIdx.x < 10) snrm[threadIdx.x] = nrm[threadIdx.x];
    __syncthreads();
    int n = blockIdx.x * blockDim.x + threadIdx.x;
    float xv[10];
#pragma unroll
    for (int c = 0; c < 10; c++) xv[c] = x[n * 10 + c] * snrm[c];
    float a[32];
#pragma unroll
    for (int o = 0; o < 32; o++) {
        float acc = sb1[o];
#pragma unroll
        for (int c = 0; c < 10; c++) acc = fmaf(xv[c], sw1[c * 32 + o], acc);
        a[o] = eluf(acc);
    }
    float ss = 0.f;
#pragma unroll 4
    for (int o = 0; o < 64; o++) {
        float acc = sb2[o];
#pragma unroll
        for (int c = 0; c < 32; c++) acc = fmaf(a[c], sw2[c * 64 + o], acc);
        acc = eluf(acc);
        h[(size_t)n * 64 + o] = acc;
        ss = fmaf(acc, acc, ss);
    }
    x2[n] = ss;
}

// ---------------- chunked brute-force kNN: partial top-8 per (query, chunk) ----------------
// grid: (N/128 qtiles, CH chunks, B batches), 128 threads = 128 queries.
template <int N>
__global__ void __launch_bounds__(128) knn_part_kernel(const float* __restrict__ h,
                                                       const float* __restrict__ x2,
                                                       float* __restrict__ part_d,
                                                       int* __restrict__ part_i) {
    __shared__ float sh[128 * 64];
    __shared__ float sx2[128];
    const int b  = blockIdx.z;
    const int ch = blockIdx.y;
    const int i  = blockIdx.x * 128 + threadIdx.x;
    const int j0 = ch * (N / CH);
    const int j1 = j0 + (N / CH);
    const float* hb = h + (size_t)b * N * 64;
    float q[64];
#pragma unroll
    for (int c = 0; c < 64; c++) q[c] = hb[(size_t)i * 64 + c];
    const float x2i = x2[b * N + i];
    float best[8];
    int bidx[8];
#pragma unroll
    for (int r = 0; r < 8; r++) { best[r] = 3e38f; bidx[r] = 0; }

    for (int jt = j0; jt < j1; jt += 128) {
        for (int idx = threadIdx.x; idx < 128 * 64; idx += 128)
            sh[idx] = hb[(size_t)jt * 64 + idx];
        sx2[threadIdx.x] = x2[b * N + jt + threadIdx.x];
        __syncthreads();
#pragma unroll 1
        for (int jj = 0; jj < 128; jj++) {
            const float* rr = &sh[jj * 64];
            float a0 = 0.f, a1 = 0.f, a2 = 0.f, a3 = 0.f;
#pragma unroll
            for (int c = 0; c < 64; c += 4) {
                a0 = fmaf(q[c + 0], rr[c + 0], a0);
                a1 = fmaf(q[c + 1], rr[c + 1], a1);
                a2 = fmaf(q[c + 2], rr[c + 2], a2);
                a3 = fmaf(q[c + 3], rr[c + 3], a3);
            }
            int j = jt + jj;
            float d = x2i + sx2[jj] - 2.f * ((a0 + a1) + (a2 + a3));
            if (d < best[7] && j != i) {
                best[7] = d; bidx[7] = j;
#pragma unroll
                for (int r = 7; r > 0; --r) {
                    if (best[r] < best[r - 1]) {
                        float tb = best[r]; best[r] = best[r - 1]; best[r - 1] = tb;
                        int ti = bidx[r]; bidx[r] = bidx[r - 1]; bidx[r - 1] = ti;
                    }
                }
            }
        }
        __syncthreads();
    }
    size_t base = (((size_t)(b * N + i)) * CH + ch) * 8;
#pragma unroll
    for (int r = 0; r < 8; r++) {
        part_d[base + r] = best[r];
        part_i[base + r] = bidx[r];
    }
}

// ---------------- merge CH sorted lists of 8 -> final top-8 ----------------
__global__ void knn_merge_kernel(const float* __restrict__ part_d,
                                 const int* __restrict__ part_i,
                                 int* __restrict__ nbr, int NB) {
    int q = blockIdx.x * blockDim.x + threadIdx.x;
    if (q >= NB) return;
    size_t base = (size_t)q * CH * 8;
    float d[CH][8]; int ix[CH][8]; int p[CH];
#pragma unroll
    for (int l = 0; l < CH; l++) {
        p[l] = 0;
#pragma unroll
        for (int r = 0; r < 8; r++) {
            d[l][r] = part_d[base + l * 8 + r];
            ix[l][r] = part_i[base + l * 8 + r];
        }
    }
#pragma unroll
    for (int r = 0; r < 8; r++) {
        float bdv = 3.1e38f; int biv = 0x7fffffff; int bl = 0;
#pragma unroll
        for (int l = 0; l < CH; l++) {
            float dv = d[l][p[l] & 7];
            int iv = ix[l][p[l] & 7];
            bool ok = (p[l] < 8) && ((dv < bdv) || (dv == bdv && iv < biv));
            if (ok) { bdv = dv; biv = iv; bl = l; }
        }
        p[bl]++;
        nbr[(size_t)q * 8 + r] = biv;
    }
}

// ---------------- per-node projections for EdgeConv decomposition ----------------
__global__ void proj_kernel(const float* __restrict__ h, const float* __restrict__ wa,
                            float* __restrict__ Pd, float* __restrict__ Ps, int NB) {
    __shared__ float Wd[64 * 96];
    __shared__ float Ws[64 * 96];
    for (int idx = threadIdx.x; idx < 64 * 96; idx += blockDim.x) {
        float top = wa[idx];
        float bot = wa[64 * 96 + idx];
        Wd[idx] = top - bot;
        Ws[idx] = bot;
    }
    __syncthreads();
    int warp = (blockIdx.x * blockDim.x + threadIdx.x) >> 5;
    int lane = threadIdx.x & 31;
    int nwarps = (gridDim.x * blockDim.x) >> 5;
    for (int n = warp; n < NB; n += nwarps) {
        float h0 = h[(size_t)n * 64 + lane];
        float h1 = h[(size_t)n * 64 + 32 + lane];
        float d0 = 0, d1 = 0, d2 = 0, s0 = 0, s1 = 0, s2 = 0;
#pragma unroll
        for (int c = 0; c < 64; c++) {
            float hc = __shfl_sync(0xffffffffu, (c < 32) ? h0 : h1, c & 31);
            const float* wd = &Wd[c * 96 + lane];
            const float* ws = &Ws[c * 96 + lane];
            d0 = fmaf(hc, wd[0], d0);  d1 = fmaf(hc, wd[32], d1);  d2 = fmaf(hc, wd[64], d2);
            s0 = fmaf(hc, ws[0], s0);  s1 = fmaf(hc, ws[32], s1);  s2 = fmaf(hc, ws[64], s2);
        }
        Pd[(size_t)n * 96 + lane] = d0; Pd[(size_t)n * 96 + lane + 32] = d1; Pd[(size_t)n * 96 + lane + 64] = d2;
        Ps[(size_t)n * 96 + lane] = s0; Ps[(size_t)n * 96 + lane + 32] = s1; Ps[(size_t)n * 96 + lane + 64] = s2;
    }
}

// ---------------- EdgeConv ----------------
__global__ void __launch_bounds__(256) edgeconv_kernel(
    const float* __restrict__ Pd, const float* __restrict__ Ps,
    const float* __restrict__ b1, const float* __restrict__ w2,
    const float* __restrict__ b2, const int* __restrict__ nbr,
    unsigned* __restrict__ agg, int Nn) {
    __shared__ float W2s[96 * 64];
    __shared__ float b2s[64];
    __shared__ float hidF[8][96];
    __shared__ float hidR[8][96];
    for (int idx = threadIdx.x; idx < 96 * 64; idx += blockDim.x) W2s[idx] = w2[idx];
    if (threadIdx.x < 64) b2s[threadIdx.x] = b2[threadIdx.x];
    __syncthreads();
    const int w = threadIdx.x >> 5, lane = threadIdx.x & 31;
    const int gn = blockIdx.x * 8 + w;
    const int b = gn / Nn;
    const float* pdi_p = Pd + (size_t)gn * 96;
    const float* psi_p = Ps + (size_t)gn * 96;
    float pdi0 = pdi_p[lane], pdi1 = pdi_p[lane + 32], pdi2 = pdi_p[lane + 64];
    float psi0 = psi_p[lane], psi1 = psi_p[lane + 32], psi2 = psi_p[lane + 64];
    float b10 = b1[lane], b11 = b1[lane + 32], b12 = b1[lane + 64];
    int nk = (lane < 8) ? nbr[(size_t)gn * 8 + lane] : 0;
    unsigned fm0 = 0u, fm1 = 0u;
#pragma unroll 1
    for (int k = 0; k < 8; k++) {
        int j = __shfl_sync(0xffffffffu, nk, k);
        size_t jg = (size_t)b * Nn + j;
        const float* pdj = Pd + jg * 96;
        const float* psj = Ps + jg * 96;
        float pj0 = pdj[lane], pj1 = pdj[lane + 32], pj2 = pdj[lane + 64];
        float sj0 = psj[lane], sj1 = psj[lane + 32], sj2 = psj[lane + 64];
        hidF[w][lane]      = eluf(pdi0 + sj0 + b10);
        hidF[w][lane + 32] = eluf(pdi1 + sj1 + b11);
        hidF[w][lane + 64] = eluf(pdi2 + sj2 + b12);
        hidR[w][lane]      = eluf(pj0 + psi0 + b10);
        hidR[w][lane + 32] = eluf(pj1 + psi1 + b11);
        hidR[w][lane + 64] = eluf(pj2 + psi2 + b12);
        __syncwarp();
        float aF0 = b2s[lane], aF1 = b2s[lane + 32];
        float aR0 = aF0, aR1 = aF1;
#pragma unroll 8
        for (int hh = 0; hh < 96; hh++) {
            float vf = hidF[w][hh], vr = hidR[w][hh];
            float w0 = W2s[hh * 64 + lane], w1 = W2s[hh * 64 + lane + 32];
            aF0 = fmaf(vf, w0, aF0); aF1 = fmaf(vf, w1, aF1);
            aR0 = fmaf(vr, w0, aR0); aR1 = fmaf(vr, w1, aR1);
        }
        __syncwarp();
        unsigned e0 = encf(eluf(aF0)), e1 = encf(eluf(aF1));
        fm0 = max(fm0, e0); fm1 = max(fm1, e1);
        atomicMax(agg + jg * 64 + lane,      encf(eluf(aR0)));
        atomicMax(agg + jg * 64 + lane + 32, encf(eluf(aR1)));
    }
    atomicMax(agg + (size_t)gn * 64 + lane,      fm0);
    atomicMax(agg + (size_t)gn * 64 + lane + 32, fm1);
}

// ---------------- decode + pairwise max pool + sq-norm ----------------
__global__ void pool_kernel(const unsigned* __restrict__ agg, float* __restrict__ h3,
                            float* __restrict__ x2b) {
    int w = (blockIdx.x * blockDim.x + threadIdx.x) >> 5;
    int lane = threadIdx.x & 31;
    int b = w / N2c;
    int i = w - b * N2c;
    size_t s0 = ((size_t)(b * N1c + 2 * i)) * 64;
    float ss = 0.f;
#pragma unroll
    for (int r = 0; r < 2; r++) {
        int c = lane + 32 * r;
        float v = fmaxf(decf(agg[s0 + c]), decf(agg[s0 + 64 + c]));
        h3[(size_t)w * 64 + c] = v;
        ss = fmaf(v, v, ss);
    }
    for (int o = 16; o > 0; o >>= 1) ss += __shfl_down_sync(0xffffffffu, ss, o);
    if (lane == 0) x2b[w] = ss;
}

// ---------------- global max pool + head MLP ----------------
__global__ void final_kernel(const unsigned* __restrict__ agg,
                             const float* __restrict__ w1, const float* __restrict__ bb1,
                             const float* __restrict__ w2, const float* __restrict__ bb2,
                             const float* __restrict__ w3, const float* __restrict__ bb3,
                             float* __restrict__ out) {
    __shared__ float red[256];
    __shared__ float gv[64], t1[64], t2[32];
    int b = blockIdx.x;
    int c = threadIdx.x & 63, grp = threadIdx.x >> 6;
    float m = -3e38f;
    for (int n = grp; n < N2c; n += 4)
        m = fmaxf(m, decf(agg[((size_t)(b * N2c + n)) * 64 + c]));
    red[threadIdx.x] = m;
    __syncthreads();
    if (threadIdx.x < 64) {
        m = fmaxf(fmaxf(red[threadIdx.x], red[threadIdx.x + 64]),
                  fmaxf(red[threadIdx.x + 128], red[threadIdx.x + 192]));
        gv[threadIdx.x] = m;
    }
    __syncthreads();
    if (threadIdx.x < 64) {
        float acc = bb1[threadIdx.x];
#pragma unroll
        for (int cc = 0; cc < 64; cc++) acc = fmaf(gv[cc], w1[cc * 64 + threadIdx.x], acc);
        t1[threadIdx.x] = eluf(acc);
    }
    __syncthreads();
    if (threadIdx.x < 32) {
        float acc = bb2[threadIdx.x];
#pragma unroll
        for (int cc = 0; cc < 64; cc++) acc = fmaf(t1[cc], w2[cc * 32 + threadIdx.x], acc);
        t2[threadIdx.x] = eluf(acc);
    }
    __syncthreads();
    if (threadIdx.x == 0) {
        float o0 = bb3[0], o1 = bb3[1];
#pragma unroll
        for (int cc = 0; cc < 32; cc++) {
            o0 = fmaf(t2[cc], w3[cc * 2 + 0], o0);
            o1 = fmaf(t2[cc], w3[cc * 2 + 1], o1);
        }
        float met = fmaxf(o0, 0.f) + log1pf(expf(-fabsf(o0)));
        float sig = 1.f / (1.f + expf(-o1));
        float phi = 3.14159265358979323846f * (2.f * sig - 1.f);
        out[b * 2 + 0] = met;
        out[b * 2 + 1] = phi;
    }
}

// ---------------- launch ----------------
extern "C" void kernel_launch(void* const* d_in, const int* in_sizes, int n_in,
                              void* d_out, int out_size) {
    const float* x      = (const float*)d_in[0];
    const float* nrm    = (const float*)d_in[1];
    const float* w_in1  = (const float*)d_in[2];
    const float* b_in1  = (const float*)d_in[3];
    const float* w_in2  = (const float*)d_in[4];
    const float* b_in2  = (const float*)d_in[5];
    const float* w_c1a  = (const float*)d_in[6];
    const float* b_c1a  = (const float*)d_in[7];
    const float* w_c1b  = (const float*)d_in[8];
    const float* b_c1b  = (const float*)d_in[9];
    const float* w_c2a  = (const float*)d_in[10];
    const float* b_c2a  = (const float*)d_in[11];
    const float* w_c2b  = (const float*)d_in[12];
    const float* b_c2b  = (const float*)d_in[13];
    const float* w_o1   = (const float*)d_in[14];
    const float* b_o1   = (const float*)d_in[15];
    const float* w_o2   = (const float*)d_in[16];
    const float* b_o2   = (const float*)d_in[17];
    const float* w_o3   = (const float*)d_in[18];
    const float* b_o3   = (const float*)d_in[19];
    float* out = (float*)d_out;

    float *h1, *x2a, *Pd1, *Ps1, *h3, *x2b, *Pd2, *Ps2, *pd1, *pd2;
    int *nbr1, *nbr2, *pi1, *pi2;
    unsigned *agg1, *agg2;
    cudaGetSymbolAddress((void**)&h1,   g_h1);
    cudaGetSymbolAddress((void**)&x2a,  g_x2a);
    cudaGetSymbolAddress((void**)&nbr1, g_nbr1);
    cudaGetSymbolAddress((void**)&Pd1,  g_Pd1);
    cudaGetSymbolAddress((void**)&Ps1,  g_Ps1);
    cudaGetSymbolAddress((void**)&agg1, g_agg1);
    cudaGetSymbolAddress((void**)&h3,   g_h3);
    cudaGetSymbolAddress((void**)&x2b,  g_x2b);
    cudaGetSymbolAddress((void**)&nbr2, g_nbr2);
    cudaGetSymbolAddress((void**)&Pd2,  g_Pd2);
    cudaGetSymbolAddress((void**)&Ps2,  g_Ps2);
    cudaGetSymbolAddress((void**)&agg2, g_agg2);
    cudaGetSymbolAddress((void**)&pd1,  g_pd1);
    cudaGetSymbolAddress((void**)&pi1,  g_pi1);
    cudaGetSymbolAddress((void**)&pd2,  g_pd2);
    cudaGetSymbolAddress((void**)&pi2,  g_pi2);

    zero_kernel<<<1024, 256>>>(agg1, Bc * N1c * Hc);
    zero_kernel<<<1024, 256>>>(agg2, Bc * N2c * Hc);

    input_mlp_kernel<<<(Bc * N1c) / 128, 128>>>(x, nrm, w_in1, b_in1, w_in2, b_in2, h1, x2a);

    knn_part_kernel<N1c><<<dim3(N1c / 128, CH, Bc), 128>>>(h1, x2a, pd1, pi1);
    knn_merge_kernel<<<(Bc * N1c + 255) / 256, 256>>>(pd1, pi1, nbr1, Bc * N1c);
    proj_kernel<<<(Bc * N1c) / 8, 256>>>(h1, w_c1a, Pd1, Ps1, Bc * N1c);
    edgeconv_kernel<<<(Bc * N1c) / 8, 256>>>(Pd1, Ps1, b_c1a, w_c1b, b_c1b, nbr1, agg1, N1c);

    pool_kernel<<<(Bc * N2c) / 8, 256>>>(agg1, h3, x2b);

    knn_part_kernel<N2c><<<dim3(N2c / 128, CH, Bc), 128>>>(h3, x2b, pd2, pi2);
    knn_merge_kernel<<<(Bc * N2c + 255) / 256, 256>>>(pd2, pi2, nbr2, Bc * N2c);
    proj_kernel<<<(Bc * N2c) / 8, 256>>>(h3, w_c2a, Pd2, Ps2, Bc * N2c);
    edgeconv_kernel<<<(Bc * N2c) / 8, 256>>>(Pd2, Ps2, b_c2a, w_c2b, b_c2b, nbr2, agg2, N2c);

    final_kernel<<<Bc, 256>>>(agg2, w_o1, b_o1, w_o2, b_o2, w_o3, b_o3, out);
}

// round 4
// speedup vs baseline: 1.3039x; 1.1025x over previous
#include <cuda_runtime.h>
#include <cuda_bf16.h>
#include <math.h>

#define Bc 8
#define N1c 4096
#define N2c 2048
#define Hc 64
#define Kc 8
#define CH 4   // candidate chunks per kNN pass

// ---------------- device scratch (no cudaMalloc allowed) ----------------
__device__ float    g_h1 [Bc*N1c*Hc];
__device__ float    g_x2a[Bc*N1c];
__device__ int      g_nbr1[Bc*N1c*Kc];
__device__ float    g_Pd1[Bc*N1c*96];
__device__ float    g_Ps1[Bc*N1c*96];
__device__ unsigned g_agg1[Bc*N1c*Hc];
__device__ float    g_h3 [Bc*N2c*Hc];
__device__ float    g_x2b[Bc*N2c];
__device__ int      g_nbr2[Bc*N2c*Kc];
__device__ float    g_Pd2[Bc*N2c*96];
__device__ float    g_Ps2[Bc*N2c*96];
__device__ unsigned g_agg2[Bc*N2c*Hc];
__device__ float    g_pd1[Bc*N1c*CH*Kc];
__device__ int      g_pi1[Bc*N1c*CH*Kc];
__device__ float    g_pd2[Bc*N2c*CH*Kc];
__device__ int      g_pi2[Bc*N2c*CH*Kc];
__device__ __nv_bfloat16 g_hh1[Bc*N1c*Hc];
__device__ __nv_bfloat16 g_hl1[Bc*N1c*Hc];
__device__ __nv_bfloat16 g_hh2[Bc*N2c*Hc];
__device__ __nv_bfloat16 g_hl2[Bc*N2c*Hc];

// ---------------- helpers ----------------
__device__ __forceinline__ float eluf(float x) { return x > 0.f ? x : expm1f(x); }

__device__ __forceinline__ unsigned encf(float f) {
    unsigned u = __float_as_uint(f);
    return (u & 0x80000000u) ? ~u : (u | 0x80000000u);
}
__device__ __forceinline__ float decf(unsigned u) {
    return __uint_as_float((u & 0x80000000u) ? (u ^ 0x80000000u) : ~u);
}

__device__ __forceinline__ void ldm4(unsigned* r, unsigned addr) {
    asm volatile("ldmatrix.sync.aligned.m8n8.x4.shared.b16 {%0,%1,%2,%3},[%4];"
                 : "=r"(r[0]), "=r"(r[1]), "=r"(r[2]), "=r"(r[3]) : "r"(addr));
}
__device__ __forceinline__ void ldm2(unsigned* r, unsigned addr) {
    asm volatile("ldmatrix.sync.aligned.m8n8.x2.shared.b16 {%0,%1},[%2];"
                 : "=r"(r[0]), "=r"(r[1]) : "r"(addr));
}
__device__ __forceinline__ void mma16816(float* c, const unsigned* a, const unsigned* b) {
    asm volatile("mma.sync.aligned.m16n8k16.row.col.f32.bf16.bf16.f32 "
                 "{%0,%1,%2,%3},{%4,%5,%6,%7},{%8,%9},{%0,%1,%2,%3};"
                 : "+f"(c[0]), "+f"(c[1]), "+f"(c[2]), "+f"(c[3])
                 : "r"(a[0]), "r"(a[1]), "r"(a[2]), "r"(a[3]), "r"(b[0]), "r"(b[1]));
}

// ---------------- zero / split ----------------
__global__ void zero_kernel(unsigned* p, int n) {
    for (int i = blockIdx.x * blockDim.x + threadIdx.x; i < n; i += gridDim.x * blockDim.x)
        p[i] = 0u;
}

__global__ void split_kernel(const float* __restrict__ in, __nv_bfloat16* __restrict__ hi,
                             __nv_bfloat16* __restrict__ lo, int n) {
    int i = blockIdx.x * blockDim.x + threadIdx.x;
    if (i < n) {
        float f = in[i];
        __nv_bfloat16 h = __float2bfloat16(f);
        hi[i] = h;
        lo[i] = __float2bfloat16(f - __bfloat162float(h));
    }
}

// ---------------- input MLP ----------------
__global__ void input_mlp_kernel(const float* __restrict__ x, const float* __restrict__ nrm,
                                 const float* __restrict__ w1, const float* __restrict__ b1,
                                 const float* __restrict__ w2, const float* __restrict__ b2,
                                 float* __restrict__ h, float* __restrict__ x2) {
    __shared__ float sw1[10 * 32], sb1[32], sw2[32 * 64], sb2[64], snrm[10];
    for (int idx = threadIdx.x; idx < 320; idx += blockDim.x) sw1[idx] = w1[idx];
    for (int idx = threadIdx.x; idx < 2048; idx += blockDim.x) sw2[idx] = w2[idx];
    if (threadIdx.x < 32) sb1[threadIdx.x] = b1[threadIdx.x];
    if (threadIdx.x < 64) sb2[threadIdx.x] = b2[threadIdx.x];
    if (threadIdx.x < 10) snrm[threadIdx.x] = nrm[threadIdx.x];
    __syncthreads();
    int n = blockIdx.x * blockDim.x + threadIdx.x;
    float xv[10];
#pragma unroll
    for (int c = 0; c < 10; c++) xv[c] = x[n * 10 + c] * snrm[c];
    float a[32];
#pragma unroll
    for (int o = 0; o < 32; o++) {
        float acc = sb1[o];
#pragma unroll
        for (int c = 0; c < 10; c++) acc = fmaf(xv[c], sw1[c * 32 + o], acc);
        a[o] = eluf(acc);
    }
    float ss = 0.f;
#pragma unroll 4
    for (int o = 0; o < 64; o++) {
        float acc = sb2[o];
#pragma unroll
        for (int c = 0; c < 32; c++) acc = fmaf(a[c], sw2[c * 64 + o], acc);
        acc = eluf(acc);
        h[(size_t)n * 64 + o] = acc;
        ss = fmaf(acc, acc, ss);
    }
    x2[n] = ss;
}

// ---------------- tensor-core chunked kNN ----------------
// smem layout (bytes): Qh 0..9216, Ql 9216..18432, Ch 18432..36864, Cl 36864..55296,
// D aliases 18432..51712 (64 x 130 f32), x2c 55296..55808.
#define SM_QH 0
#define SM_QL 9216
#define SM_CH 18432
#define SM_CL 36864
#define SM_D  18432
#define SM_X2 55296
#define KNN_SMEM 55808
#define TS 144      // tile row stride bytes (72 bf16)
#define DSTR 520    // D row stride bytes (130 f32)

template <int N>
__global__ void __launch_bounds__(128) knn_mma_kernel(
    const __nv_bfloat16* __restrict__ hh, const __nv_bfloat16* __restrict__ hl,
    const float* __restrict__ x2, float* __restrict__ part_d, int* __restrict__ part_i) {
    extern __shared__ unsigned char sm_raw[];
    const unsigned sb = (unsigned)__cvta_generic_to_shared(sm_raw);
    const int b = blockIdx.z, ch = blockIdx.y;
    const int i0 = blockIdx.x * 64;
    const int tid = threadIdx.x, lane = tid & 31, w = tid >> 5;
    const int j0 = ch * (N / CH), j1 = j0 + (N / CH);
    const __nv_bfloat16* hhb = hh + (size_t)b * N * 64;
    const __nv_bfloat16* hlb = hl + (size_t)b * N * 64;

    // load Q tiles (64 rows x 64 bf16, padded stride 72)
    for (int idx = tid; idx < 64 * 8; idx += 128) {
        int r = idx >> 3, c = idx & 7;
        *(uint4*)(sm_raw + SM_QH + r * TS + c * 16) = *(const uint4*)(hhb + (size_t)(i0 + r) * 64 + c * 8);
        *(uint4*)(sm_raw + SM_QL + r * TS + c * 16) = *(const uint4*)(hlb + (size_t)(i0 + r) * 64 + c * 8);
    }

    const int qrow = tid & 63, chalf = tid >> 6;
    const float x2i = x2[b * N + i0 + qrow];
    const int self = i0 + qrow;
    float bd[8]; int bix[8];
#pragma unroll
    for (int r = 0; r < 8; r++) { bd[r] = 3e38f; bix[r] = 0; }

    // ldmatrix per-lane offsets
    const int sub = lane >> 3, l7 = lane & 7;
    const int arow = 16 * w + l7 + ((sub & 1) ? 8 : 0);
    const unsigned aoff = (unsigned)(arow * TS + ((sub >> 1) ? 16 : 0));
    const unsigned boff = (unsigned)(l7 * TS + (((lane >> 3) & 1) ? 16 : 0));

    for (int jt = j0; jt < j1; jt += 128) {
        for (int idx = tid; idx < 128 * 8; idx += 128) {
            int r = idx >> 3, c = idx & 7;
            *(uint4*)(sm_raw + SM_CH + r * TS + c * 16) = *(const uint4*)(hhb + (size_t)(jt + r) * 64 + c * 8);
            *(uint4*)(sm_raw + SM_CL + r * TS + c * 16) = *(const uint4*)(hlb + (size_t)(jt + r) * 64 + c * 8);
        }
        ((float*)(sm_raw + SM_X2))[tid] = x2[b * N + jt + tid];
        __syncthreads();

        float acc[16][4];
#pragma unroll
        for (int nt = 0; nt < 16; nt++)
#pragma unroll
            for (int e = 0; e < 4; e++) acc[nt][e] = 0.f;

#pragma unroll 1
        for (int ks = 0; ks < 4; ks++) {
            unsigned ah[4], al[4];
            ldm4(ah, sb + SM_QH + aoff + ks * 32);
            ldm4(al, sb + SM_QL + aoff + ks * 32);
            unsigned bah = sb + SM_CH + boff + ks * 32;
            unsigned bal = sb + SM_CL + boff + ks * 32;
#pragma unroll
            for (int nt = 0; nt < 16; nt++) {
                unsigned bh[2], bl[2];
                ldm2(bh, bah); ldm2(bl, bal);
                mma16816(acc[nt], ah, bh);
                mma16816(acc[nt], al, bh);
                mma16816(acc[nt], ah, bl);
                bah += 8 * TS; bal += 8 * TS;
            }
        }
        __syncthreads();   // all ldmatrix reads done before aliased D stores

        const int drow = 16 * w + (lane >> 2);
        const int dcol = (lane & 3) * 2;
#pragma unroll
        for (int nt = 0; nt < 16; nt++) {
            *(float2*)(sm_raw + SM_D + drow * DSTR + (8 * nt + dcol) * 4) = make_float2(acc[nt][0], acc[nt][1]);
            *(float2*)(sm_raw + SM_D + (drow + 8) * DSTR + (8 * nt + dcol) * 4) = make_float2(acc[nt][2], acc[nt][3]);
        }
        __syncthreads();

        // phase B: scan 64 candidates (this thread's half)
        const float* drp = (const float*)(sm_raw + SM_D + qrow * DSTR) + chalf * 64;
        const float* sx = (const float*)(sm_raw + SM_X2) + chalf * 64;
        const int jb = jt + chalf * 64;
#pragma unroll 1
        for (int jj = 0; jj < 64; jj++) {
            float d = x2i + sx[jj] - 2.f * drp[jj];
            int j = jb + jj;
            if (d < bd[7] && j != self) {
                bd[7] = d; bix[7] = j;
#pragma unroll
                for (int r = 7; r > 0; --r) {
                    if (bd[r] < bd[r - 1]) {
                        float tb = bd[r]; bd[r] = bd[r - 1]; bd[r - 1] = tb;
                        int ti = bix[r]; bix[r] = bix[r - 1]; bix[r - 1] = ti;
                    }
                }
            }
        }
        __syncthreads();   // before next tile overwrites C/D
    }

    // merge the two half-lists per query (lexicographic (d, idx)), write partials
    float* stg = (float*)sm_raw;   // reuse Qh region (4KB needed)
    if (chalf == 1) {
#pragma unroll
        for (int r = 0; r < 8; r++) {
            stg[qrow * 16 + r] = bd[r];
            ((int*)stg)[qrow * 16 + 8 + r] = bix[r];
        }
    }
    __syncthreads();
    if (chalf == 0) {
        size_t base = (((size_t)(b * N + i0 + qrow)) * CH + ch) * 8;
        int pa = 0, pb = 0;
#pragma unroll
        for (int r = 0; r < 8; r++) {
            float da = bd[pa]; int ia = bix[pa];
            float db = stg[qrow * 16 + pb]; int ib = ((int*)stg)[qrow * 16 + 8 + pb];
            bool ta = (da < db) || (da == db && ia < ib);
            part_d[base + r] = ta ? da : db;
            part_i[base + r] = ta ? ia : ib;
            if (ta) pa++; else pb++;
        }
    }
}

// ---------------- merge CH sorted lists of 8 -> final top-8 ----------------
__global__ void knn_merge_kernel(const float* __restrict__ part_d,
                                 const int* __restrict__ part_i,
                                 int* __restrict__ nbr, int NB) {
    int q = blockIdx.x * blockDim.x + threadIdx.x;
    if (q >= NB) return;
    size_t base = (size_t)q * CH * 8;
    float d[CH][8]; int ix[CH][8]; int p[CH];
#pragma unroll
    for (int l = 0; l < CH; l++) {
        p[l] = 0;
#pragma unroll
        for (int r = 0; r < 8; r++) {
            d[l][r] = part_d[base + l * 8 + r];
            ix[l][r] = part_i[base + l * 8 + r];
        }
    }
#pragma unroll
    for (int r = 0; r < 8; r++) {
        float bdv = 3.1e38f; int biv = 0x7fffffff; int bl = 0;
#pragma unroll
        for (int l = 0; l < CH; l++) {
            float dv = d[l][p[l] & 7];
            int iv = ix[l][p[l] & 7];
            bool ok = (p[l] < 8) && ((dv < bdv) || (dv == bdv && iv < biv));
            if (ok) { bdv = dv; biv = iv; bl = l; }
        }
        p[bl]++;
        nbr[(size_t)q * 8 + r] = biv;
    }
}

// ---------------- per-node projections for EdgeConv decomposition ----------------
__global__ void proj_kernel(const float* __restrict__ h, const float* __restrict__ wa,
                            float* __restrict__ Pd, float* __restrict__ Ps, int NB) {
    __shared__ float Wd[64 * 96];
    __shared__ float Ws[64 * 96];
    for (int idx = threadIdx.x; idx < 64 * 96; idx += blockDim.x) {
        float top = wa[idx];
        float bot = wa[64 * 96 + idx];
        Wd[idx] = top - bot;
        Ws[idx] = bot;
    }
    __syncthreads();
    int warp = (blockIdx.x * blockDim.x + threadIdx.x) >> 5;
    int lane = threadIdx.x & 31;
    int nwarps = (gridDim.x * blockDim.x) >> 5;
    for (int n = warp; n < NB; n += nwarps) {
        float h0 = h[(size_t)n * 64 + lane];
        float h1 = h[(size_t)n * 64 + 32 + lane];
        float d0 = 0, d1 = 0, d2 = 0, s0 = 0, s1 = 0, s2 = 0;
#pragma unroll
        for (int c = 0; c < 64; c++) {
            float hc = __shfl_sync(0xffffffffu, (c < 32) ? h0 : h1, c & 31);
            const float* wd = &Wd[c * 96 + lane];
            const float* ws = &Ws[c * 96 + lane];
            d0 = fmaf(hc, wd[0], d0);  d1 = fmaf(hc, wd[32], d1);  d2 = fmaf(hc, wd[64], d2);
            s0 = fmaf(hc, ws[0], s0);  s1 = fmaf(hc, ws[32], s1);  s2 = fmaf(hc, ws[64], s2);
        }
        Pd[(size_t)n * 96 + lane] = d0; Pd[(size_t)n * 96 + lane + 32] = d1; Pd[(size_t)n * 96 + lane + 64] = d2;
        Ps[(size_t)n * 96 + lane] = s0; Ps[(size_t)n * 96 + lane + 32] = s1; Ps[(size_t)n * 96 + lane + 64] = s2;
    }
}

// ---------------- EdgeConv ----------------
__global__ void __launch_bounds__(256) edgeconv_kernel(
    const float* __restrict__ Pd, const float* __restrict__ Ps,
    const float* __restrict__ b1, const float* __restrict__ w2,
    const float* __restrict__ b2, const int* __restrict__ nbr,
    unsigned* __restrict__ agg, int Nn) {
    __shared__ float W2s[96 * 64];
    __shared__ float b2s[64];
    __shared__ float hidF[8][96];
    __shared__ float hidR[8][96];
    for (int idx = threadIdx.x; idx < 96 * 64; idx += blockDim.x) W2s[idx] = w2[idx];
    if (threadIdx.x < 64) b2s[threadIdx.x] = b2[threadIdx.x];
    __syncthreads();
    const int w = threadIdx.x >> 5, lane = threadIdx.x & 31;
    const int gn = blockIdx.x * 8 + w;
    const int b = gn / Nn;
    const float* pdi_p = Pd + (size_t)gn * 96;
    const float* psi_p = Ps + (size_t)gn * 96;
    float pdi0 = pdi_p[lane], pdi1 = pdi_p[lane + 32], pdi2 = pdi_p[lane + 64];
    float psi0 = psi_p[lane], psi1 = psi_p[lane + 32], psi2 = psi_p[lane + 64];
    float b10 = b1[lane], b11 = b1[lane + 32], b12 = b1[lane + 64];
    int nk = (lane < 8) ? nbr[(size_t)gn * 8 + lane] : 0;
    unsigned fm0 = 0u, fm1 = 0u;
#pragma unroll 1
    for (int k = 0; k < 8; k++) {
        int j = __shfl_sync(0xffffffffu, nk, k);
        size_t jg = (size_t)b * Nn + j;
        const float* pdj = Pd + jg * 96;
        const float* psj = Ps + jg * 96;
        float pj0 = pdj[lane], pj1 = pdj[lane + 32], pj2 = pdj[lane + 64];
        float sj0 = psj[lane], sj1 = psj[lane + 32], sj2 = psj[lane + 64];
        hidF[w][lane]      = eluf(pdi0 + sj0 + b10);
        hidF[w][lane + 32] = eluf(pdi1 + sj1 + b11);
        hidF[w][lane + 64] = eluf(pdi2 + sj2 + b12);
        hidR[w][lane]      = eluf(pj0 + psi0 + b10);
        hidR[w][lane + 32] = eluf(pj1 + psi1 + b11);
        hidR[w][lane + 64] = eluf(pj2 + psi2 + b12);
        __syncwarp();
        float aF0 = b2s[lane], aF1 = b2s[lane + 32];
        float aR0 = aF0, aR1 = aF1;
#pragma unroll 8
        for (int hh = 0; hh < 96; hh++) {
            float vf = hidF[w][hh], vr = hidR[w][hh];
            float w0 = W2s[hh * 64 + lane], w1 = W2s[hh * 64 + lane + 32];
            aF0 = fmaf(vf, w0, aF0); aF1 = fmaf(vf, w1, aF1);
            aR0 = fmaf(vr, w0, aR0); aR1 = fmaf(vr, w1, aR1);
        }
        __syncwarp();
        unsigned e0 = encf(eluf(aF0)), e1 = encf(eluf(aF1));
        fm0 = max(fm0, e0); fm1 = max(fm1, e1);
        atomicMax(agg + jg * 64 + lane,      encf(eluf(aR0)));
        atomicMax(agg + jg * 64 + lane + 32, encf(eluf(aR1)));
    }
    atomicMax(agg + (size_t)gn * 64 + lane,      fm0);
    atomicMax(agg + (size_t)gn * 64 + lane + 32, fm1);
}

// ---------------- decode + pairwise max pool + sq-norm ----------------
__global__ void pool_kernel(const unsigned* __restrict__ agg, float* __restrict__ h3,
                            float* __restrict__ x2b) {
    int w = (blockIdx.x * blockDim.x + threadIdx.x) >> 5;
    int lane = threadIdx.x & 31;
    int b = w / N2c;
    int i = w - b * N2c;
    size_t s0 = ((size_t)(b * N1c + 2 * i)) * 64;
    float ss = 0.f;
#pragma unroll
    for (int r = 0; r < 2; r++) {
        int c = lane + 32 * r;
        float v = fmaxf(decf(agg[s0 + c]), decf(agg[s0 + 64 + c]));
        h3[(size_t)w * 64 + c] = v;
        ss = fmaf(v, v, ss);
    }
    for (int o = 16; o > 0; o >>= 1) ss += __shfl_down_sync(0xffffffffu, ss, o);
    if (lane == 0) x2b[w] = ss;
}

// ---------------- global max pool + head MLP ----------------
__global__ void final_kernel(const unsigned* __restrict__ agg,
                             const float* __restrict__ w1, const float* __restrict__ bb1,
                             const float* __restrict__ w2, const float* __restrict__ bb2,
                             const float* __restrict__ w3, const float* __restrict__ bb3,
                             float* __restrict__ out) {
    __shared__ float red[256];
    __shared__ float gv[64], t1[64], t2[32];
    int b = blockIdx.x;
    int c = threadIdx.x & 63, grp = threadIdx.x >> 6;
    float m = -3e38f;
    for (int n = grp; n < N2c; n += 4)
        m = fmaxf(m, decf(agg[((size_t)(b * N2c + n)) * 64 + c]));
    red[threadIdx.x] = m;
    __syncthreads();
    if (threadIdx.x < 64) {
        m = fmaxf(fmaxf(red[threadIdx.x], red[threadIdx.x + 64]),
                  fmaxf(red[threadIdx.x + 128], red[threadIdx.x + 192]));
        gv[threadIdx.x] = m;
    }
    __syncthreads();
    if (threadIdx.x < 64) {
        float acc = bb1[threadIdx.x];
#pragma unroll
        for (int cc = 0; cc < 64; cc++) acc = fmaf(gv[cc], w1[cc * 64 + threadIdx.x], acc);
        t1[threadIdx.x] = eluf(acc);
    }
    __syncthreads();
    if (threadIdx.x < 32) {
        float acc = bb2[threadIdx.x];
#pragma unroll
        for (int cc = 0; cc < 64; cc++) acc = fmaf(t1[cc], w2[cc * 32 + threadIdx.x], acc);
        t2[threadIdx.x] = eluf(acc);
    }
    __syncthreads();
    if (threadIdx.x == 0) {
        float o0 = bb3[0], o1 = bb3[1];
#pragma unroll
        for (int cc = 0; cc < 32; cc++) {
            o0 = fmaf(t2[cc], w3[cc * 2 + 0], o0);
            o1 = fmaf(t2[cc], w3[cc * 2 + 1], o1);
        }
        float met = fmaxf(o0, 0.f) + log1pf(expf(-fabsf(o0)));
        float sig = 1.f / (1.f + expf(-o1));
        float phi = 3.14159265358979323846f * (2.f * sig - 1.f);
        out[b * 2 + 0] = met;
        out[b * 2 + 1] = phi;
    }
}

// ---------------- launch ----------------
extern "C" void kernel_launch(void* const* d_in, const int* in_sizes, int n_in,
                              void* d_out, int out_size) {
    const float* x      = (const float*)d_in[0];
    const float* nrm    = (const float*)d_in[1];
    const float* w_in1  = (const float*)d_in[2];
    const float* b_in1  = (const float*)d_in[3];
    const float* w_in2  = (const float*)d_in[4];
    const float* b_in2  = (const float*)d_in[5];
    const float* w_c1a  = (const float*)d_in[6];
    const float* b_c1a  = (const float*)d_in[7];
    const float* w_c1b  = (const float*)d_in[8];
    const float* b_c1b  = (const float*)d_in[9];
    const float* w_c2a  = (const float*)d_in[10];
    const float* b_c2a  = (const float*)d_in[11];
    const float* w_c2b  = (const float*)d_in[12];
    const float* b_c2b  = (const float*)d_in[13];
    const float* w_o1   = (const float*)d_in[14];
    const float* b_o1   = (const float*)d_in[15];
    const float* w_o2   = (const float*)d_in[16];
    const float* b_o2   = (const float*)d_in[17];
    const float* w_o3   = (const float*)d_in[18];
    const float* b_o3   = (const float*)d_in[19];
    float* out = (float*)d_out;

    float *h1, *x2a, *Pd1, *Ps1, *h3, *x2b, *Pd2, *Ps2, *pd1, *pd2;
    int *nbr1, *nbr2, *pi1, *pi2;
    unsigned *agg1, *agg2;
    __nv_bfloat16 *hh1, *hl1, *hh2, *hl2;
    cudaGetSymbolAddress((void**)&h1,   g_h1);
    cudaGetSymbolAddress((void**)&x2a,  g_x2a);
    cudaGetSymbolAddress((void**)&nbr1, g_nbr1);
    cudaGetSymbolAddress((void**)&Pd1,  g_Pd1);
    cudaGetSymbolAddress((void**)&Ps1,  g_Ps1);
    cudaGetSymbolAddress((void**)&agg1, g_agg1);
    cudaGetSymbolAddress((void**)&h3,   g_h3);
    cudaGetSymbolAddress((void**)&x2b,  g_x2b);
    cudaGetSymbolAddress((void**)&nbr2, g_nbr2);
    cudaGetSymbolAddress((void**)&Pd2,  g_Pd2);
    cudaGetSymbolAddress((void**)&Ps2,  g_Ps2);
    cudaGetSymbolAddress((void**)&agg2, g_agg2);
    cudaGetSymbolAddress((void**)&pd1,  g_pd1);
    cudaGetSymbolAddress((void**)&pi1,  g_pi1);
    cudaGetSymbolAddress((void**)&pd2,  g_pd2);
    cudaGetSymbolAddress((void**)&pi2,  g_pi2);
    cudaGetSymbolAddress((void**)&hh1,  g_hh1);
    cudaGetSymbolAddress((void**)&hl1,  g_hl1);
    cudaGetSymbolAddress((void**)&hh2,  g_hh2);
    cudaGetSymbolAddress((void**)&hl2,  g_hl2);

    cudaFuncSetAttribute(knn_mma_kernel<N1c>, cudaFuncAttributeMaxDynamicSharedMemorySize, KNN_SMEM);
    cudaFuncSetAttribute(knn_mma_kernel<N2c>, cudaFuncAttributeMaxDynamicSharedMemorySize, KNN_SMEM);

    zero_kernel<<<1024, 256>>>(agg1, Bc * N1c * Hc);
    zero_kernel<<<1024, 256>>>(agg2, Bc * N2c * Hc);

    input_mlp_kernel<<<(Bc * N1c) / 128, 128>>>(x, nrm, w_in1, b_in1, w_in2, b_in2, h1, x2a);
    split_kernel<<<(Bc * N1c * Hc + 255) / 256, 256>>>(h1, hh1, hl1, Bc * N1c * Hc);

    knn_mma_kernel<N1c><<<dim3(N1c / 64, CH, Bc), 128, KNN_SMEM>>>(hh1, hl1, x2a, pd1, pi1);
    knn_merge_kernel<<<(Bc * N1c + 255) / 256, 256>>>(pd1, pi1, nbr1, Bc * N1c);
    proj_kernel<<<(Bc * N1c) / 8, 256>>>(h1, w_c1a, Pd1, Ps1, Bc * N1c);
    edgeconv_kernel<<<(Bc * N1c) / 8, 256>>>(Pd1, Ps1, b_c1a, w_c1b, b_c1b, nbr1, agg1, N1c);

    pool_kernel<<<(Bc * N2c) / 8, 256>>>(agg1, h3, x2b);
    split_kernel<<<(Bc * N2c * Hc + 255) / 256, 256>>>(h3, hh2, hl2, Bc * N2c * Hc);

    knn_mma_kernel<N2c><<<dim3(N2c / 64, CH, Bc), 128, KNN_SMEM>>>(hh2, hl2, x2b, pd2, pi2);
    knn_merge_kernel<<<(Bc * N2c + 255) / 256, 256>>>(pd2, pi2, nbr2, Bc * N2c);
    proj_kernel<<<(Bc * N2c) / 8, 256>>>(h3, w_c2a, Pd2, Ps2, Bc * N2c);
    edgeconv_kernel<<<(Bc * N2c) / 8, 256>>>(Pd2, Ps2, b_c2a, w_c2b, b_c2b, nbr2, agg2, N2c);

    final_kernel<<<Bc, 256>>>(agg2, w_o1, b_o1, w_o2, b_o2, w_o3, b_o3, out);
}

// round 5
// speedup vs baseline: 1.3818x; 1.0597x over previous
#include <cuda_runtime.h>
#include <cuda_bf16.h>
#include <math.h>

#define Bc 8
#define N1c 4096
#define N2c 2048
#define Hc 64
#define Kc 8
#define CH 4   // candidate chunks per kNN pass

// ---------------- device scratch (no cudaMalloc allowed) ----------------
__device__ float    g_h1 [Bc*N1c*Hc];
__device__ float    g_x2a[Bc*N1c];
__device__ int      g_nbr1[Bc*N1c*Kc];
__device__ float    g_Pd1[Bc*N1c*96];
__device__ float    g_Ps1[Bc*N1c*96];
__device__ unsigned g_agg1[Bc*N1c*Hc];
__device__ float    g_h3 [Bc*N2c*Hc];
__device__ float    g_x2b[Bc*N2c];
__device__ int      g_nbr2[Bc*N2c*Kc];
__device__ float    g_Pd2[Bc*N2c*96];
__device__ float    g_Ps2[Bc*N2c*96];
__device__ unsigned g_agg2[Bc*N2c*Hc];
__device__ float    g_pd1[Bc*N1c*CH*Kc];
__device__ int      g_pi1[Bc*N1c*CH*Kc];
__device__ float    g_pd2[Bc*N2c*CH*Kc];
__device__ int      g_pi2[Bc*N2c*CH*Kc];
__device__ __nv_bfloat16 g_hh1[Bc*N1c*Hc];
__device__ __nv_bfloat16 g_hl1[Bc*N1c*Hc];
__device__ __nv_bfloat16 g_hh2[Bc*N2c*Hc];
__device__ __nv_bfloat16 g_hl2[Bc*N2c*Hc];

// ---------------- helpers ----------------
__device__ __forceinline__ float eluf(float x) { return x > 0.f ? x : expm1f(x); }

__device__ __forceinline__ unsigned encf(float f) {
    unsigned u = __float_as_uint(f);
    return (u & 0x80000000u) ? ~u : (u | 0x80000000u);
}
__device__ __forceinline__ float decf(unsigned u) {
    return __uint_as_float((u & 0x80000000u) ? (u ^ 0x80000000u) : ~u);
}

__device__ __forceinline__ void ldm4(unsigned* r, unsigned addr) {
    asm volatile("ldmatrix.sync.aligned.m8n8.x4.shared.b16 {%0,%1,%2,%3},[%4];"
                 : "=r"(r[0]), "=r"(r[1]), "=r"(r[2]), "=r"(r[3]) : "r"(addr));
}
__device__ __forceinline__ void ldm2(unsigned* r, unsigned addr) {
    asm volatile("ldmatrix.sync.aligned.m8n8.x2.shared.b16 {%0,%1},[%2];"
                 : "=r"(r[0]), "=r"(r[1]) : "r"(addr));
}
__device__ __forceinline__ void mma16816(float* c, const unsigned* a, const unsigned* b) {
    asm volatile("mma.sync.aligned.m16n8k16.row.col.f32.bf16.bf16.f32 "
                 "{%0,%1,%2,%3},{%4,%5,%6,%7},{%8,%9},{%0,%1,%2,%3};"
                 : "+f"(c[0]), "+f"(c[1]), "+f"(c[2]), "+f"(c[3])
                 : "r"(a[0]), "r"(a[1]), "r"(a[2]), "r"(a[3]), "r"(b[0]), "r"(b[1]));
}

// ---------------- zero / split ----------------
__global__ void zero_kernel(unsigned* p, int n) {
    for (int i = blockIdx.x * blockDim.x + threadIdx.x; i < n; i += gridDim.x * blockDim.x)
        p[i] = 0u;
}

__global__ void split_kernel(const float* __restrict__ in, __nv_bfloat16* __restrict__ hi,
                             __nv_bfloat16* __restrict__ lo, int n) {
    int i = blockIdx.x * blockDim.x + threadIdx.x;
    if (i < n) {
        float f = in[i];
        __nv_bfloat16 h = __float2bfloat16(f);
        hi[i] = h;
        lo[i] = __float2bfloat16(f - __bfloat162float(h));
    }
}

// ---------------- input MLP ----------------
__global__ void input_mlp_kernel(const float* __restrict__ x, const float* __restrict__ nrm,
                                 const float* __restrict__ w1, const float* __restrict__ b1,
                                 const float* __restrict__ w2, const float* __restrict__ b2,
                                 float* __restrict__ h, float* __restrict__ x2) {
    __shared__ float sw1[10 * 32], sb1[32], sw2[32 * 64], sb2[64], snrm[10];
    for (int idx = threadIdx.x; idx < 320; idx += blockDim.x) sw1[idx] = w1[idx];
    for (int idx = threadIdx.x; idx < 2048; idx += blockDim.x) sw2[idx] = w2[idx];
    if (threadIdx.x < 32) sb1[threadIdx.x] = b1[threadIdx.x];
    if (threadIdx.x < 64) sb2[threadIdx.x] = b2[threadIdx.x];
    if (threadIdx.x < 10) snrm[threadIdx.x] = nrm[threadIdx.x];
    __syncthreads();
    int n = blockIdx.x * blockDim.x + threadIdx.x;
    float xv[10];
#pragma unroll
    for (int c = 0; c < 10; c++) xv[c] = x[n * 10 + c] * snrm[c];
    float a[32];
#pragma unroll
    for (int o = 0; o < 32; o++) {
        float acc = sb1[o];
#pragma unroll
        for (int c = 0; c < 10; c++) acc = fmaf(xv[c], sw1[c * 32 + o], acc);
        a[o] = eluf(acc);
    }
    float ss = 0.f;
#pragma unroll 4
    for (int o = 0; o < 64; o++) {
        float acc = sb2[o];
#pragma unroll
        for (int c = 0; c < 32; c++) acc = fmaf(a[c], sw2[c * 64 + o], acc);
        acc = eluf(acc);
        h[(size_t)n * 64 + o] = acc;
        ss = fmaf(acc, acc, ss);
    }
    x2[n] = ss;
}

// ---------------- tensor-core chunked kNN ----------------
#define SM_QH 0
#define SM_QL 9216
#define SM_CH 18432
#define SM_CL 36864
#define SM_D  18432
#define SM_X2 55296
#define KNN_SMEM 55808
#define TS 144
#define DSTR 520

template <int N>
__global__ void __launch_bounds__(128) knn_mma_kernel(
    const __nv_bfloat16* __restrict__ hh, const __nv_bfloat16* __restrict__ hl,
    const float* __restrict__ x2, float* __restrict__ part_d, int* __restrict__ part_i) {
    extern __shared__ unsigned char sm_raw[];
    const unsigned sb = (unsigned)__cvta_generic_to_shared(sm_raw);
    const int b = blockIdx.z, ch = blockIdx.y;
    const int i0 = blockIdx.x * 64;
    const int tid = threadIdx.x, lane = tid & 31, w = tid >> 5;
    const int j0 = ch * (N / CH), j1 = j0 + (N / CH);
    const __nv_bfloat16* hhb = hh + (size_t)b * N * 64;
    const __nv_bfloat16* hlb = hl + (size_t)b * N * 64;

    for (int idx = tid; idx < 64 * 8; idx += 128) {
        int r = idx >> 3, c = idx & 7;
        *(uint4*)(sm_raw + SM_QH + r * TS + c * 16) = *(const uint4*)(hhb + (size_t)(i0 + r) * 64 + c * 8);
        *(uint4*)(sm_raw + SM_QL + r * TS + c * 16) = *(const uint4*)(hlb + (size_t)(i0 + r) * 64 + c * 8);
    }

    const int qrow = tid & 63, chalf = tid >> 6;
    const float x2i = x2[b * N + i0 + qrow];
    const int self = i0 + qrow;
    float bd[8]; int bix[8];
#pragma unroll
    for (int r = 0; r < 8; r++) { bd[r] = 3e38f; bix[r] = 0; }

    const int sub = lane >> 3, l7 = lane & 7;
    const int arow = 16 * w + l7 + ((sub & 1) ? 8 : 0);
    const unsigned aoff = (unsigned)(arow * TS + ((sub >> 1) ? 16 : 0));
    const unsigned boff = (unsigned)(l7 * TS + (((lane >> 3) & 1) ? 16 : 0));

    for (int jt = j0; jt < j1; jt += 128) {
        for (int idx = tid; idx < 128 * 8; idx += 128) {
            int r = idx >> 3, c = idx & 7;
            *(uint4*)(sm_raw + SM_CH + r * TS + c * 16) = *(const uint4*)(hhb + (size_t)(jt + r) * 64 + c * 8);
            *(uint4*)(sm_raw + SM_CL + r * TS + c * 16) = *(const uint4*)(hlb + (size_t)(jt + r) * 64 + c * 8);
        }
        ((float*)(sm_raw + SM_X2))[tid] = x2[b * N + jt + tid];
        __syncthreads();

        float acc[16][4];
#pragma unroll
        for (int nt = 0; nt < 16; nt++)
#pragma unroll
            for (int e = 0; e < 4; e++) acc[nt][e] = 0.f;

#pragma unroll 1
        for (int ks = 0; ks < 4; ks++) {
            unsigned ah[4], al[4];
            ldm4(ah, sb + SM_QH + aoff + ks * 32);
            ldm4(al, sb + SM_QL + aoff + ks * 32);
            unsigned bah = sb + SM_CH + boff + ks * 32;
            unsigned bal = sb + SM_CL + boff + ks * 32;
#pragma unroll
            for (int nt = 0; nt < 16; nt++) {
                unsigned bh[2], bl[2];
                ldm2(bh, bah); ldm2(bl, bal);
                mma16816(acc[nt], ah, bh);
                mma16816(acc[nt], al, bh);
                mma16816(acc[nt], ah, bl);
                bah += 8 * TS; bal += 8 * TS;
            }
        }
        __syncthreads();

        const int drow = 16 * w + (lane >> 2);
        const int dcol = (lane & 3) * 2;
#pragma unroll
        for (int nt = 0; nt < 16; nt++) {
            *(float2*)(sm_raw + SM_D + drow * DSTR + (8 * nt + dcol) * 4) = make_float2(acc[nt][0], acc[nt][1]);
            *(float2*)(sm_raw + SM_D + (drow + 8) * DSTR + (8 * nt + dcol) * 4) = make_float2(acc[nt][2], acc[nt][3]);
        }
        __syncthreads();

        const float* drp = (const float*)(sm_raw + SM_D + qrow * DSTR) + chalf * 64;
        const float* sx = (const float*)(sm_raw + SM_X2) + chalf * 64;
        const int jb = jt + chalf * 64;
#pragma unroll 1
        for (int jj = 0; jj < 64; jj++) {
            float d = x2i + sx[jj] - 2.f * drp[jj];
            int j = jb + jj;
            if (d < bd[7] && j != self) {
                bd[7] = d; bix[7] = j;
#pragma unroll
                for (int r = 7; r > 0; --r) {
                    if (bd[r] < bd[r - 1]) {
                        float tb = bd[r]; bd[r] = bd[r - 1]; bd[r - 1] = tb;
                        int ti = bix[r]; bix[r] = bix[r - 1]; bix[r - 1] = ti;
                    }
                }
            }
        }
        __syncthreads();
    }

    float* stg = (float*)sm_raw;
    if (chalf == 1) {
#pragma unroll
        for (int r = 0; r < 8; r++) {
            stg[qrow * 16 + r] = bd[r];
            ((int*)stg)[qrow * 16 + 8 + r] = bix[r];
        }
    }
    __syncthreads();
    if (chalf == 0) {
        size_t base = (((size_t)(b * N + i0 + qrow)) * CH + ch) * 8;
        int pa = 0, pb = 0;
#pragma unroll
        for (int r = 0; r < 8; r++) {
            float da = bd[pa]; int ia = bix[pa];
            float db = stg[qrow * 16 + pb]; int ib = ((int*)stg)[qrow * 16 + 8 + pb];
            bool ta = (da < db) || (da == db && ia < ib);
            part_d[base + r] = ta ? da : db;
            part_i[base + r] = ta ? ia : ib;
            if (ta) pa++; else pb++;
        }
    }
}

// ---------------- merge CH sorted lists of 8 -> final top-8 ----------------
__global__ void knn_merge_kernel(const float* __restrict__ part_d,
                                 const int* __restrict__ part_i,
                                 int* __restrict__ nbr, int NB) {
    int q = blockIdx.x * blockDim.x + threadIdx.x;
    if (q >= NB) return;
    size_t base = (size_t)q * CH * 8;
    float d[CH][8]; int ix[CH][8]; int p[CH];
#pragma unroll
    for (int l = 0; l < CH; l++) {
        p[l] = 0;
#pragma unroll
        for (int r = 0; r < 8; r++) {
            d[l][r] = part_d[base + l * 8 + r];
            ix[l][r] = part_i[base + l * 8 + r];
        }
    }
#pragma unroll
    for (int r = 0; r < 8; r++) {
        float bdv = 3.1e38f; int biv = 0x7fffffff; int bl = 0;
#pragma unroll
        for (int l = 0; l < CH; l++) {
            float dv = d[l][p[l] & 7];
            int iv = ix[l][p[l] & 7];
            bool ok = (p[l] < 8) && ((dv < bdv) || (dv == bdv && iv < biv));
            if (ok) { bdv = dv; biv = iv; bl = l; }
        }
        p[bl]++;
        nbr[(size_t)q * 8 + r] = biv;
    }
}

// ---------------- per-node projections for EdgeConv decomposition ----------------
__global__ void proj_kernel(const float* __restrict__ h, const float* __restrict__ wa,
                            float* __restrict__ Pd, float* __restrict__ Ps, int NB) {
    __shared__ float Wd[64 * 96];
    __shared__ float Ws[64 * 96];
    for (int idx = threadIdx.x; idx < 64 * 96; idx += blockDim.x) {
        float top = wa[idx];
        float bot = wa[64 * 96 + idx];
        Wd[idx] = top - bot;
        Ws[idx] = bot;
    }
    __syncthreads();
    int warp = (blockIdx.x * blockDim.x + threadIdx.x) >> 5;
    int lane = threadIdx.x & 31;
    int nwarps = (gridDim.x * blockDim.x) >> 5;
    for (int n = warp; n < NB; n += nwarps) {
        float h0 = h[(size_t)n * 64 + lane];
        float h1 = h[(size_t)n * 64 + 32 + lane];
        float d0 = 0, d1 = 0, d2 = 0, s0 = 0, s1 = 0, s2 = 0;
#pragma unroll
        for (int c = 0; c < 64; c++) {
            float hc = __shfl_sync(0xffffffffu, (c < 32) ? h0 : h1, c & 31);
            const float* wd = &Wd[c * 96 + lane];
            const float* ws = &Ws[c * 96 + lane];
            d0 = fmaf(hc, wd[0], d0);  d1 = fmaf(hc, wd[32], d1);  d2 = fmaf(hc, wd[64], d2);
            s0 = fmaf(hc, ws[0], s0);  s1 = fmaf(hc, ws[32], s1);  s2 = fmaf(hc, ws[64], s2);
        }
        Pd[(size_t)n * 96 + lane] = d0; Pd[(size_t)n * 96 + lane + 32] = d1; Pd[(size_t)n * 96 + lane + 64] = d2;
        Ps[(size_t)n * 96 + lane] = s0; Ps[(size_t)n * 96 + lane + 32] = s1; Ps[(size_t)n * 96 + lane + 64] = s2;
    }
}

// ---------------- EdgeConv: register-blocked (one warp = one node, 16 messages at once) ----------------
// dyn smem: sW2 (float2[96*32], 24KB) then sHid [8 warps][2][96 rows][8 edges] floats (48KB)
#define EC_SMEM (96*32*8 + 8*2*96*8*4)
__global__ void __launch_bounds__(256, 2) edgeconv_kernel(
    const float* __restrict__ Pd, const float* __restrict__ Ps,
    const float* __restrict__ b1, const float* __restrict__ w2,
    const float* __restrict__ b2, const int* __restrict__ nbr,
    unsigned* __restrict__ agg, int Nn) {
    extern __shared__ unsigned char ec_sm[];
    float2* sW2 = (float2*)ec_sm;                       // [96*32]
    float*  sHidBase = (float*)(ec_sm + 96 * 32 * 8);   // [8][2][96][8]

    for (int idx = threadIdx.x; idx < 96 * 32; idx += 256)
        sW2[idx] = ((const float2*)w2)[idx];

    const int w = threadIdx.x >> 5, lane = threadIdx.x & 31;
    const int gn = blockIdx.x * 8 + w;
    const int b = gn / Nn;
    float* sF = sHidBase + (size_t)w * 2 * 96 * 8;      // [96][8]
    float* sR = sF + 96 * 8;

    const float* pdi_p = Pd + (size_t)gn * 96;
    const float* psi_p = Ps + (size_t)gn * 96;
    float pdi0 = pdi_p[lane], pdi1 = pdi_p[lane + 32], pdi2 = pdi_p[lane + 64];
    float psi0 = psi_p[lane], psi1 = psi_p[lane + 32], psi2 = psi_p[lane + 64];
    float b10 = b1[lane], b11 = b1[lane + 32], b12 = b1[lane + 64];

    int jn[8];
#pragma unroll
    for (int k = 0; k < 8; k++) jn[k] = nbr[(size_t)gn * 8 + k];

    // stage hidden-layer messages: sF[row][k] = eluf(Pd_i[row] + Ps_j[row] + b1[row]); sR uses Pd_j + Ps_i
#pragma unroll 1
    for (int k = 0; k < 8; k++) {
        size_t jg = (size_t)b * Nn + jn[k];
        const float* pdj = Pd + jg * 96;
        const float* psj = Ps + jg * 96;
        float pj0 = pdj[lane], pj1 = pdj[lane + 32], pj2 = pdj[lane + 64];
        float sj0 = psj[lane], sj1 = psj[lane + 32], sj2 = psj[lane + 64];
        sF[lane * 8 + k]        = eluf(pdi0 + sj0 + b10);
        sF[(lane + 32) * 8 + k] = eluf(pdi1 + sj1 + b11);
        sF[(lane + 64) * 8 + k] = eluf(pdi2 + sj2 + b12);
        sR[lane * 8 + k]        = eluf(pj0 + psi0 + b10);
        sR[(lane + 32) * 8 + k] = eluf(pj1 + psi1 + b11);
        sR[(lane + 64) * 8 + k] = eluf(pj2 + psi2 + b12);
    }
    __syncthreads();   // sW2 ready + own warp's sHid written (warp-local, but cheap)

    // main loop: 16 messages x 2 output cols per lane
    float aF[8][2], aR[8][2];
#pragma unroll
    for (int e = 0; e < 8; e++) { aF[e][0] = aF[e][1] = aR[e][0] = aR[e][1] = 0.f; }

#pragma unroll 4
    for (int hh = 0; hh < 96; hh++) {
        float2 wv = sW2[hh * 32 + lane];
        float4 f03 = *(const float4*)&sF[hh * 8];
        float4 f47 = *(const float4*)&sF[hh * 8 + 4];
        float4 r03 = *(const float4*)&sR[hh * 8];
        float4 r47 = *(const float4*)&sR[hh * 8 + 4];
        aF[0][0] = fmaf(f03.x, wv.x, aF[0][0]); aF[0][1] = fmaf(f03.x, wv.y, aF[0][1]);
        aF[1][0] = fmaf(f03.y, wv.x, aF[1][0]); aF[1][1] = fmaf(f03.y, wv.y, aF[1][1]);
        aF[2][0] = fmaf(f03.z, wv.x, aF[2][0]); aF[2][1] = fmaf(f03.z, wv.y, aF[2][1]);
        aF[3][0] = fmaf(f03.w, wv.x, aF[3][0]); aF[3][1] = fmaf(f03.w, wv.y, aF[3][1]);
        aF[4][0] = fmaf(f47.x, wv.x, aF[4][0]); aF[4][1] = fmaf(f47.x, wv.y, aF[4][1]);
        aF[5][0] = fmaf(f47.y, wv.x, aF[5][0]); aF[5][1] = fmaf(f47.y, wv.y, aF[5][1]);
        aF[6][0] = fmaf(f47.z, wv.x, aF[6][0]); aF[6][1] = fmaf(f47.z, wv.y, aF[6][1]);
        aF[7][0] = fmaf(f47.w, wv.x, aF[7][0]); aF[7][1] = fmaf(f47.w, wv.y, aF[7][1]);
        aR[0][0] = fmaf(r03.x, wv.x, aR[0][0]); aR[0][1] = fmaf(r03.x, wv.y, aR[0][1]);
        aR[1][0] = fmaf(r03.y, wv.x, aR[1][0]); aR[1][1] = fmaf(r03.y, wv.y, aR[1][1]);
        aR[2][0] = fmaf(r03.z, wv.x, aR[2][0]); aR[2][1] = fmaf(r03.z, wv.y, aR[2][1]);
        aR[3][0] = fmaf(r03.w, wv.x, aR[3][0]); aR[3][1] = fmaf(r03.w, wv.y, aR[3][1]);
        aR[4][0] = fmaf(r47.x, wv.x, aR[4][0]); aR[4][1] = fmaf(r47.x, wv.y, aR[4][1]);
        aR[5][0] = fmaf(r47.y, wv.x, aR[5][0]); aR[5][1] = fmaf(r47.y, wv.y, aR[5][1]);
        aR[6][0] = fmaf(r47.z, wv.x, aR[6][0]); aR[6][1] = fmaf(r47.z, wv.y, aR[6][1]);
        aR[7][0] = fmaf(r47.w, wv.x, aR[7][0]); aR[7][1] = fmaf(r47.w, wv.y, aR[7][1]);
    }

    // epilogue: +bias, elu, encode, scatter-max
    const float bo0 = b2[2 * lane], bo1 = b2[2 * lane + 1];
    unsigned fm0 = 0u, fm1 = 0u;
#pragma unroll
    for (int e = 0; e < 8; e++) {
        fm0 = max(fm0, encf(eluf(aF[e][0] + bo0)));
        fm1 = max(fm1, encf(eluf(aF[e][1] + bo1)));
    }
    atomicMax(agg + (size_t)gn * 64 + 2 * lane,     fm0);
    atomicMax(agg + (size_t)gn * 64 + 2 * lane + 1, fm1);
#pragma unroll
    for (int e = 0; e < 8; e++) {
        size_t jg = (size_t)b * Nn + jn[e];
        atomicMax(agg + jg * 64 + 2 * lane,     encf(eluf(aR[e][0] + bo0)));
        atomicMax(agg + jg * 64 + 2 * lane + 1, encf(eluf(aR[e][1] + bo1)));
    }
}

// ---------------- decode + pairwise max pool + sq-norm ----------------
__global__ void pool_kernel(const unsigned* __restrict__ agg, float* __restrict__ h3,
                            float* __restrict__ x2b) {
    int w = (blockIdx.x * blockDim.x + threadIdx.x) >> 5;
    int lane = threadIdx.x & 31;
    int b = w / N2c;
    int i = w - b * N2c;
    size_t s0 = ((size_t)(b * N1c + 2 * i)) * 64;
    float ss = 0.f;
#pragma unroll
    for (int r = 0; r < 2; r++) {
        int c = lane + 32 * r;
        float v = fmaxf(decf(agg[s0 + c]), decf(agg[s0 + 64 + c]));
        h3[(size_t)w * 64 + c] = v;
        ss = fmaf(v, v, ss);
    }
    for (int o = 16; o > 0; o >>= 1) ss += __shfl_down_sync(0xffffffffu, ss, o);
    if (lane == 0) x2b[w] = ss;
}

// ---------------- global max pool + head MLP ----------------
__global__ void final_kernel(const unsigned* __restrict__ agg,
                             const float* __restrict__ w1, const float* __restrict__ bb1,
                             const float* __restrict__ w2, const float* __restrict__ bb2,
                             const float* __restrict__ w3, const float* __restrict__ bb3,
                             float* __restrict__ out) {
    __shared__ float red[256];
    __shared__ float gv[64], t1[64], t2[32];
    int b = blockIdx.x;
    int c = threadIdx.x & 63, grp = threadIdx.x >> 6;
    float m = -3e38f;
    for (int n = grp; n < N2c; n += 4)
        m = fmaxf(m, decf(agg[((size_t)(b * N2c + n)) * 64 + c]));
    red[threadIdx.x] = m;
    __syncthreads();
    if (threadIdx.x < 64) {
        m = fmaxf(fmaxf(red[threadIdx.x], red[threadIdx.x + 64]),
                  fmaxf(red[threadIdx.x + 128], red[threadIdx.x + 192]));
        gv[threadIdx.x] = m;
    }
    __syncthreads();
    if (threadIdx.x < 64) {
        float acc = bb1[threadIdx.x];
#pragma unroll
        for (int cc = 0; cc < 64; cc++) acc = fmaf(gv[cc], w1[cc * 64 + threadIdx.x], acc);
        t1[threadIdx.x] = eluf(acc);
    }
    __syncthreads();
    if (threadIdx.x < 32) {
        float acc = bb2[threadIdx.x];
#pragma unroll
        for (int cc = 0; cc < 64; cc++) acc = fmaf(t1[cc], w2[cc * 32 + threadIdx.x], acc);
        t2[threadIdx.x] = eluf(acc);
    }
    __syncthreads();
    if (threadIdx.x == 0) {
        float o0 = bb3[0], o1 = bb3[1];
#pragma unroll
        for (int cc = 0; cc < 32; cc++) {
            o0 = fmaf(t2[cc], w3[cc * 2 + 0], o0);
            o1 = fmaf(t2[cc], w3[cc * 2 + 1], o1);
        }
        float met = fmaxf(o0, 0.f) + log1pf(expf(-fabsf(o0)));
        float sig = 1.f / (1.f + expf(-o1));
        float phi = 3.14159265358979323846f * (2.f * sig - 1.f);
        out[b * 2 + 0] = met;
        out[b * 2 + 1] = phi;
    }
}

// ---------------- launch ----------------
extern "C" void kernel_launch(void* const* d_in, const int* in_sizes, int n_in,
                              void* d_out, int out_size) {
    const float* x      = (const float*)d_in[0];
    const float* nrm    = (const float*)d_in[1];
    const float* w_in1  = (const float*)d_in[2];
    const float* b_in1  = (const float*)d_in[3];
    const float* w_in2  = (const float*)d_in[4];
    const float* b_in2  = (const float*)d_in[5];
    const float* w_c1a  = (const float*)d_in[6];
    const float* b_c1a  = (const float*)d_in[7];
    const float* w_c1b  = (const float*)d_in[8];
    const float* b_c1b  = (const float*)d_in[9];
    const float* w_c2a  = (const float*)d_in[10];
    const float* b_c2a  = (const float*)d_in[11];
    const float* w_c2b  = (const float*)d_in[12];
    const float* b_c2b  = (const float*)d_in[13];
    const float* w_o1   = (const float*)d_in[14];
    const float* b_o1   = (const float*)d_in[15];
    const float* w_o2   = (const float*)d_in[16];
    const float* b_o2   = (const float*)d_in[17];
    const float* w_o3   = (const float*)d_in[18];
    const float* b_o3   = (const float*)d_in[19];
    float* out = (float*)d_out;

    float *h1, *x2a, *Pd1, *Ps1, *h3, *x2b, *Pd2, *Ps2, *pd1, *pd2;
    int *nbr1, *nbr2, *pi1, *pi2;
    unsigned *agg1, *agg2;
    __nv_bfloat16 *hh1, *hl1, *hh2, *hl2;
    cudaGetSymbolAddress((void**)&h1,   g_h1);
    cudaGetSymbolAddress((void**)&x2a,  g_x2a);
    cudaGetSymbolAddress((void**)&nbr1, g_nbr1);
    cudaGetSymbolAddress((void**)&Pd1,  g_Pd1);
    cudaGetSymbolAddress((void**)&Ps1,  g_Ps1);
    cudaGetSymbolAddress((void**)&agg1, g_agg1);
    cudaGetSymbolAddress((void**)&h3,   g_h3);
    cudaGetSymbolAddress((void**)&x2b,  g_x2b);
    cudaGetSymbolAddress((void**)&nbr2, g_nbr2);
    cudaGetSymbolAddress((void**)&Pd2,  g_Pd2);
    cudaGetSymbolAddress((void**)&Ps2,  g_Ps2);
    cudaGetSymbolAddress((void**)&agg2, g_agg2);
    cudaGetSymbolAddress((void**)&pd1,  g_pd1);
    cudaGetSymbolAddress((void**)&pi1,  g_pi1);
    cudaGetSymbolAddress((void**)&pd2,  g_pd2);
    cudaGetSymbolAddress((void**)&pi2,  g_pi2);
    cudaGetSymbolAddress((void**)&hh1,  g_hh1);
    cudaGetSymbolAddress((void**)&hl1,  g_hl1);
    cudaGetSymbolAddress((void**)&hh2,  g_hh2);
    cudaGetSymbolAddress((void**)&hl2,  g_hl2);

    cudaFuncSetAttribute(knn_mma_kernel<N1c>, cudaFuncAttributeMaxDynamicSharedMemorySize, KNN_SMEM);
    cudaFuncSetAttribute(knn_mma_kernel<N2c>, cudaFuncAttributeMaxDynamicSharedMemorySize, KNN_SMEM);
    cudaFuncSetAttribute(edgeconv_kernel, cudaFuncAttributeMaxDynamicSharedMemorySize, EC_SMEM);

    zero_kernel<<<1024, 256>>>(agg1, Bc * N1c * Hc);
    zero_kernel<<<1024, 256>>>(agg2, Bc * N2c * Hc);

    input_mlp_kernel<<<(Bc * N1c) / 128, 128>>>(x, nrm, w_in1, b_in1, w_in2, b_in2, h1, x2a);
    split_kernel<<<(Bc * N1c * Hc + 255) / 256, 256>>>(h1, hh1, hl1, Bc * N1c * Hc);

    knn_mma_kernel<N1c><<<dim3(N1c / 64, CH, Bc), 128, KNN_SMEM>>>(hh1, hl1, x2a, pd1, pi1);
    knn_merge_kernel<<<(Bc * N1c + 255) / 256, 256>>>(pd1, pi1, nbr1, Bc * N1c);
    proj_kernel<<<(Bc * N1c) / 8, 256>>>(h1, w_c1a, Pd1, Ps1, Bc * N1c);
    edgeconv_kernel<<<(Bc * N1c) / 8, 256, EC_SMEM>>>(Pd1, Ps1, b_c1a, w_c1b, b_c1b, nbr1, agg1, N1c);

    pool_kernel<<<(Bc * N2c) / 8, 256>>>(agg1, h3, x2b);
    split_kernel<<<(Bc * N2c * Hc + 255) / 256, 256>>>(h3, hh2, hl2, Bc * N2c * Hc);

    knn_mma_kernel<N2c><<<dim3(N2c / 64, CH, Bc), 128, KNN_SMEM>>>(hh2, hl2, x2b, pd2, pi2);
    knn_merge_kernel<<<(Bc * N2c + 255) / 256, 256>>>(pd2, pi2, nbr2, Bc * N2c);
    proj_kernel<<<(Bc * N2c) / 8, 256>>>(h3, w_c2a, Pd2, Ps2, Bc * N2c);
    edgeconv_kernel<<<(Bc * N2c) / 8, 256, EC_SMEM>>>(Pd2, Ps2, b_c2a, w_c2b, b_c2b, nbr2, agg2, N2c);

    final_kernel<<<Bc, 256>>>(agg2, w_o1, b_o1, w_o2, b_o2, w_o3, b_o3, out);
}